// round 1
// baseline (speedup 1.0000x reference)
#include <cuda_runtime.h>
#include <math.h>

#define M_TOK 4096   // B*S
#define DMODEL 1024
#define NHEAD 16
#define HDIM 64

// Scratch: Q, K, V, attn-out, proj-out  (5 x 16 MB)
__device__ float g_scratch[5][(size_t)M_TOK * DMODEL];

// ---------------------------------------------------------------------------
// NT GEMM: C[m,n] = alpha * (sum_k A[m,k] * B[n,k] + bias[n])
// BM=BN=128, BK=16, 256 threads, 8x8 micro-tile per thread.
// ---------------------------------------------------------------------------
__global__ __launch_bounds__(256) void gemm_nt(
    const float* __restrict__ A, const float* __restrict__ B,
    const float* __restrict__ bias, float* __restrict__ C,
    int M, int N, int K, float alpha)
{
    __shared__ float As[16][128];
    __shared__ float Bs[16][128];

    const int m0 = blockIdx.y * 128;
    const int n0 = blockIdx.x * 128;
    const int tid = threadIdx.x;
    const int tx = tid & 15;
    const int ty = tid >> 4;

    float acc[8][8];
#pragma unroll
    for (int i = 0; i < 8; i++)
#pragma unroll
        for (int j = 0; j < 8; j++) acc[i][j] = 0.f;

    for (int kt = 0; kt < K; kt += 16) {
#pragma unroll
        for (int p = 0; p < 2; p++) {
            int f   = tid + p * 256;   // 0..511
            int row = f >> 2;          // 0..127
            int c4  = (f & 3) << 2;    // 0,4,8,12
            float4 va = *(const float4*)(A + (size_t)(m0 + row) * K + kt + c4);
            As[c4 + 0][row] = va.x; As[c4 + 1][row] = va.y;
            As[c4 + 2][row] = va.z; As[c4 + 3][row] = va.w;
            float4 vb = *(const float4*)(B + (size_t)(n0 + row) * K + kt + c4);
            Bs[c4 + 0][row] = vb.x; Bs[c4 + 1][row] = vb.y;
            Bs[c4 + 2][row] = vb.z; Bs[c4 + 3][row] = vb.w;
        }
        __syncthreads();

#pragma unroll
        for (int k = 0; k < 16; k++) {
            float a[8], b[8];
            *(float4*)&a[0] = *(const float4*)&As[k][ty * 8];
            *(float4*)&a[4] = *(const float4*)&As[k][ty * 8 + 4];
            *(float4*)&b[0] = *(const float4*)&Bs[k][tx * 8];
            *(float4*)&b[4] = *(const float4*)&Bs[k][tx * 8 + 4];
#pragma unroll
            for (int i = 0; i < 8; i++)
#pragma unroll
                for (int j = 0; j < 8; j++) acc[i][j] += a[i] * b[j];
        }
        __syncthreads();
    }

    float bj[8];
#pragma unroll
    for (int j = 0; j < 8; j++) bj[j] = bias[n0 + tx * 8 + j];

#pragma unroll
    for (int i = 0; i < 8; i++) {
        size_t r = (size_t)(m0 + ty * 8 + i) * N + n0 + tx * 8;
        float4 o0, o1;
        o0.x = alpha * (acc[i][0] + bj[0]); o0.y = alpha * (acc[i][1] + bj[1]);
        o0.z = alpha * (acc[i][2] + bj[2]); o0.w = alpha * (acc[i][3] + bj[3]);
        o1.x = alpha * (acc[i][4] + bj[4]); o1.y = alpha * (acc[i][5] + bj[5]);
        o1.z = alpha * (acc[i][6] + bj[6]); o1.w = alpha * (acc[i][7] + bj[7]);
        *(float4*)(C + r)     = o0;
        *(float4*)(C + r + 4) = o1;
    }
}

// ---------------------------------------------------------------------------
// Flash-style causal attention. One CTA = (b, h, 64-query tile).
// 256 threads as 16x16 grid; strided 4x4 micro-tiles:
//   rows  r_i = i*16 + ty, cols c_j = j*16 + tx  (conflict-free smem frags)
// Online softmax, O accumulated in registers.
// ---------------------------------------------------------------------------
__global__ __launch_bounds__(256) void attn_kernel(
    const float* __restrict__ Q, const float* __restrict__ K,
    const float* __restrict__ V, float* __restrict__ O)
{
    extern __shared__ float sm[];
    float* Qs = sm;                 // 64 x 64
    float* Ks = sm + 64 * 64;       // 64 x 65 (padded)
    float* Vs = Ks + 64 * 65;       // 64 x 64
    float* Ps = Vs + 64 * 64;       // 64 x 64

    const int qt = blockIdx.x;
    const int h  = blockIdx.y;
    const int b  = blockIdx.z;
    const int qbase = qt * 64;
    const int tid = threadIdx.x;
    const int tx = tid & 15;
    const int ty = tid >> 4;
    const size_t tokbase = (size_t)b * 2048;

    // Load Q tile (rows = tokens, cols = head dims)
#pragma unroll
    for (int p = 0; p < 4; p++) {
        int f = tid + p * 256;
        int row = f >> 4;
        int c = (f & 15) << 2;
        float4 v = *(const float4*)(Q + (tokbase + qbase + row) * DMODEL + h * HDIM + c);
        *(float4*)&Qs[row * 64 + c] = v;
    }

    float acc[4][4];
#pragma unroll
    for (int i = 0; i < 4; i++)
#pragma unroll
        for (int j = 0; j < 4; j++) acc[i][j] = 0.f;
    float mrow[4], lrow[4];
#pragma unroll
    for (int i = 0; i < 4; i++) { mrow[i] = -INFINITY; lrow[i] = 0.f; }

    __syncthreads();

    for (int kt = 0; kt <= qt; kt++) {
        const int kbase = kt * 64;
        // Load K (padded, transpose-free) and V tiles
#pragma unroll
        for (int p = 0; p < 4; p++) {
            int f = tid + p * 256;
            int row = f >> 4;
            int c = (f & 15) << 2;
            float4 vk = *(const float4*)(K + (tokbase + kbase + row) * DMODEL + h * HDIM + c);
            Ks[row * 65 + c + 0] = vk.x; Ks[row * 65 + c + 1] = vk.y;
            Ks[row * 65 + c + 2] = vk.z; Ks[row * 65 + c + 3] = vk.w;
            float4 vv = *(const float4*)(V + (tokbase + kbase + row) * DMODEL + h * HDIM + c);
            *(float4*)&Vs[row * 64 + c] = vv;
        }
        __syncthreads();

        // S = Q K^T (64x64 tile), 4x4 per thread
        float s[4][4];
#pragma unroll
        for (int i = 0; i < 4; i++)
#pragma unroll
            for (int j = 0; j < 4; j++) s[i][j] = 0.f;

#pragma unroll 8
        for (int d = 0; d < 64; d++) {
            float a0 = Qs[(0 * 16 + ty) * 64 + d];
            float a1 = Qs[(1 * 16 + ty) * 64 + d];
            float a2 = Qs[(2 * 16 + ty) * 64 + d];
            float a3 = Qs[(3 * 16 + ty) * 64 + d];
            float b0 = Ks[(0 * 16 + tx) * 65 + d];
            float b1 = Ks[(1 * 16 + tx) * 65 + d];
            float b2 = Ks[(2 * 16 + tx) * 65 + d];
            float b3 = Ks[(3 * 16 + tx) * 65 + d];
            s[0][0] += a0 * b0; s[0][1] += a0 * b1; s[0][2] += a0 * b2; s[0][3] += a0 * b3;
            s[1][0] += a1 * b0; s[1][1] += a1 * b1; s[1][2] += a1 * b2; s[1][3] += a1 * b3;
            s[2][0] += a2 * b0; s[2][1] += a2 * b1; s[2][2] += a2 * b2; s[2][3] += a2 * b3;
            s[3][0] += a3 * b0; s[3][1] += a3 * b1; s[3][2] += a3 * b2; s[3][3] += a3 * b3;
        }

        if (kt == qt) {  // causal mask only on the diagonal tile
#pragma unroll
            for (int i = 0; i < 4; i++)
#pragma unroll
                for (int j = 0; j < 4; j++)
                    if (j * 16 + tx > i * 16 + ty) s[i][j] = -INFINITY;
        }

        // Online softmax update per row (4 rows per thread; reduce over 16 lanes)
#pragma unroll
        for (int i = 0; i < 4; i++) {
            float mt = fmaxf(fmaxf(s[i][0], s[i][1]), fmaxf(s[i][2], s[i][3]));
#pragma unroll
            for (int off = 1; off < 16; off <<= 1)
                mt = fmaxf(mt, __shfl_xor_sync(0xffffffffu, mt, off, 16));
            float mn = fmaxf(mrow[i], mt);
            float corr = __expf(mrow[i] - mn);
            mrow[i] = mn;
            float rs = 0.f;
#pragma unroll
            for (int j = 0; j < 4; j++) {
                float p = __expf(s[i][j] - mn);
                Ps[(i * 16 + ty) * 64 + j * 16 + tx] = p;
                rs += p;
            }
#pragma unroll
            for (int off = 1; off < 16; off <<= 1)
                rs += __shfl_xor_sync(0xffffffffu, rs, off, 16);
            lrow[i] = lrow[i] * corr + rs;
#pragma unroll
            for (int j = 0; j < 4; j++) acc[i][j] *= corr;
        }
        __syncwarp();  // P row writers/readers share a warp; cross-warp not needed

        // O += P V   (4x4 per thread)
#pragma unroll 8
        for (int k = 0; k < 64; k++) {
            float p0 = Ps[(0 * 16 + ty) * 64 + k];
            float p1 = Ps[(1 * 16 + ty) * 64 + k];
            float p2 = Ps[(2 * 16 + ty) * 64 + k];
            float p3 = Ps[(3 * 16 + ty) * 64 + k];
            float v0 = Vs[k * 64 + 0 * 16 + tx];
            float v1 = Vs[k * 64 + 1 * 16 + tx];
            float v2 = Vs[k * 64 + 2 * 16 + tx];
            float v3 = Vs[k * 64 + 3 * 16 + tx];
            acc[0][0] += p0 * v0; acc[0][1] += p0 * v1; acc[0][2] += p0 * v2; acc[0][3] += p0 * v3;
            acc[1][0] += p1 * v0; acc[1][1] += p1 * v1; acc[1][2] += p1 * v2; acc[1][3] += p1 * v3;
            acc[2][0] += p2 * v0; acc[2][1] += p2 * v1; acc[2][2] += p2 * v2; acc[2][3] += p2 * v3;
            acc[3][0] += p3 * v0; acc[3][1] += p3 * v1; acc[3][2] += p3 * v2; acc[3][3] += p3 * v3;
        }
        __syncthreads();  // before next tile overwrites Ks/Vs
    }

#pragma unroll
    for (int i = 0; i < 4; i++) {
        float inv = 1.f / lrow[i];
#pragma unroll
        for (int j = 0; j < 4; j++)
            O[(tokbase + qbase + i * 16 + ty) * DMODEL + h * HDIM + j * 16 + tx] =
                acc[i][j] * inv;
    }
}

// ---------------------------------------------------------------------------
// Residual add + LayerNorm, one block per token row.
// ---------------------------------------------------------------------------
__global__ __launch_bounds__(256) void ln_kernel(
    const float* __restrict__ Osrc, const float* __restrict__ X,
    const float* __restrict__ g, const float* __restrict__ beta,
    float* __restrict__ out)
{
    const int row = blockIdx.x;
    const int tid = threadIdx.x;
    const float* o = Osrc + (size_t)row * DMODEL;
    const float* x = X + (size_t)row * DMODEL;

    float v[4];
    float s = 0.f, s2 = 0.f;
#pragma unroll
    for (int i = 0; i < 4; i++) {
        int c = tid + i * 256;
        float t = o[c] + x[c];
        v[i] = t; s += t; s2 += t * t;
    }
#pragma unroll
    for (int off = 16; off; off >>= 1) {
        s  += __shfl_xor_sync(0xffffffffu, s, off);
        s2 += __shfl_xor_sync(0xffffffffu, s2, off);
    }
    __shared__ float red[18];
    int w = tid >> 5;
    if ((tid & 31) == 0) { red[w] = s; red[8 + w] = s2; }
    __syncthreads();
    if (tid == 0) {
        float S = 0.f, S2 = 0.f;
        for (int k = 0; k < 8; k++) { S += red[k]; S2 += red[8 + k]; }
        red[16] = S; red[17] = S2;
    }
    __syncthreads();
    float mu   = red[16] * (1.f / 1024.f);
    float var  = red[17] * (1.f / 1024.f) - mu * mu;
    float rstd = rsqrtf(var + 1e-5f);
#pragma unroll
    for (int i = 0; i < 4; i++) {
        int c = tid + i * 256;
        out[(size_t)row * DMODEL + c] = (v[i] - mu) * rstd * g[c] + beta[c];
    }
}

// ---------------------------------------------------------------------------
extern "C" void kernel_launch(void* const* d_in, const int* in_sizes, int n_in,
                              void* d_out, int out_size)
{
    const float* X  = (const float*)d_in[0];
    const float* Wq = (const float*)d_in[1];
    const float* bq = (const float*)d_in[2];
    const float* Wk = (const float*)d_in[3];
    const float* bk = (const float*)d_in[4];
    const float* Wv = (const float*)d_in[5];
    const float* bv = (const float*)d_in[6];
    const float* Wo = (const float*)d_in[7];
    const float* bo = (const float*)d_in[8];
    const float* lg = (const float*)d_in[9];
    const float* lb = (const float*)d_in[10];
    float* out = (float*)d_out;

    float* base = nullptr;
    cudaGetSymbolAddress((void**)&base, g_scratch);
    float* Qb = base + (size_t)0 * M_TOK * DMODEL;
    float* Kb = base + (size_t)1 * M_TOK * DMODEL;
    float* Vb = base + (size_t)2 * M_TOK * DMODEL;
    float* Ab = base + (size_t)3 * M_TOK * DMODEL;
    float* Ob = base + (size_t)4 * M_TOK * DMODEL;

    const float scale = 0.125f;  // HD^-0.5, HD=64

    dim3 ggrid(DMODEL / 128, M_TOK / 128);
    gemm_nt<<<ggrid, 256>>>(X, Wq, bq, Qb, M_TOK, DMODEL, DMODEL, scale);
    gemm_nt<<<ggrid, 256>>>(X, Wk, bk, Kb, M_TOK, DMODEL, DMODEL, 1.f);
    gemm_nt<<<ggrid, 256>>>(X, Wv, bv, Vb, M_TOK, DMODEL, DMODEL, 1.f);

    const int smem = (64 * 64 * 3 + 64 * 65) * (int)sizeof(float);  // 65792 B
    cudaFuncSetAttribute(attn_kernel, cudaFuncAttributeMaxDynamicSharedMemorySize, smem);
    attn_kernel<<<dim3(32, NHEAD, 2), 256, smem>>>(Qb, Kb, Vb, Ab);

    gemm_nt<<<ggrid, 256>>>(Ab, Wo, bo, Ob, M_TOK, DMODEL, DMODEL, 1.f);
    ln_kernel<<<M_TOK, 256>>>(Ob, X, lg, lb, out);
}

// round 3
// speedup vs baseline: 1.5495x; 1.5495x over previous
#include <cuda_runtime.h>
#include <cuda_bf16.h>
#include <cstdint>
#include <math.h>

#define M_TOK 4096   // B*S
#define DMODEL 1024
#define NHEAD 16
#define HDIM 64

// fp32 scratch: Q, K, V, attn-out, proj-out
__device__ float g_f32[5][(size_t)M_TOK * DMODEL];
// bf16 hi/lo split operands
__device__ __nv_bfloat16 g_xhi[(size_t)M_TOK * DMODEL], g_xlo[(size_t)M_TOK * DMODEL];
__device__ __nv_bfloat16 g_ahi[(size_t)M_TOK * DMODEL], g_alo[(size_t)M_TOK * DMODEL];
__device__ __nv_bfloat16 g_whi[4][(size_t)DMODEL * DMODEL], g_wlo[4][(size_t)DMODEL * DMODEL];

// ---------------------------------------------------------------------------
// PTX helpers valid on base sm_103 target (no tcgen05!)
// ---------------------------------------------------------------------------
__device__ __forceinline__ uint32_t smem_to_u32(const void* p) {
    uint32_t a;
    asm("{ .reg .u64 t; cvta.to.shared.u64 t, %1; cvt.u32.u64 %0, t; }" : "=r"(a) : "l"(p));
    return a;
}
__device__ __forceinline__ void cp16(uint32_t dst, const void* src) {
    asm volatile("cp.async.cg.shared.global [%0], [%1], 16;" :: "r"(dst), "l"(src));
}
__device__ __forceinline__ void ldsm4(uint32_t* r, uint32_t addr) {
    asm volatile("ldmatrix.sync.aligned.m8n8.x4.shared.b16 {%0,%1,%2,%3}, [%4];"
                 : "=r"(r[0]), "=r"(r[1]), "=r"(r[2]), "=r"(r[3]) : "r"(addr));
}
__device__ __forceinline__ void mma16816(float* c, const uint32_t* a, const uint32_t* b) {
    asm volatile(
        "mma.sync.aligned.m16n8k16.row.col.f32.bf16.bf16.f32 "
        "{%0,%1,%2,%3}, {%4,%5,%6,%7}, {%8,%9}, {%0,%1,%2,%3};"
        : "+f"(c[0]), "+f"(c[1]), "+f"(c[2]), "+f"(c[3])
        : "r"(a[0]), "r"(a[1]), "r"(a[2]), "r"(a[3]), "r"(b[0]), "r"(b[1]));
}

// ---------------------------------------------------------------------------
// fp32 -> bf16 hi/lo split (x = hi + lo + O(2^-18 x))
// ---------------------------------------------------------------------------
__global__ __launch_bounds__(256) void split_bf16(
    const float* __restrict__ x, __nv_bfloat16* __restrict__ hi,
    __nv_bfloat16* __restrict__ lo, int n4)
{
    int i = blockIdx.x * 256 + threadIdx.x;
    if (i >= n4) return;
    float4 v = *(const float4*)(x + (size_t)i * 4);
    __nv_bfloat16 h0 = __float2bfloat16(v.x), h1 = __float2bfloat16(v.y);
    __nv_bfloat16 h2 = __float2bfloat16(v.z), h3 = __float2bfloat16(v.w);
    __nv_bfloat16 l0 = __float2bfloat16(v.x - __bfloat162float(h0));
    __nv_bfloat16 l1 = __float2bfloat16(v.y - __bfloat162float(h1));
    __nv_bfloat16 l2 = __float2bfloat16(v.z - __bfloat162float(h2));
    __nv_bfloat16 l3 = __float2bfloat16(v.w - __bfloat162float(h3));
    __nv_bfloat162* hp = (__nv_bfloat162*)(hi + (size_t)i * 4);
    __nv_bfloat162* lp = (__nv_bfloat162*)(lo + (size_t)i * 4);
    hp[0] = __nv_bfloat162(h0, h1); hp[1] = __nv_bfloat162(h2, h3);
    lp[0] = __nv_bfloat162(l0, l1); lp[1] = __nv_bfloat162(l2, l3);
}

// ---------------------------------------------------------------------------
// HMMA NT GEMM with bf16 hi/lo compensation (3 passes).
// C[m,n] = alpha * (sum_k A[m,k]*B[n,k] + bias[n]).  M=4096, N=1024, K=1024.
// CTA: 128x128 tile, BK=32, 256 threads (8 warps, 2x4), warp tile 64x32.
// smem stage (40960 B): Ahi@0, Alo@10240, Bhi@20480, Blo@30720;
// each tile 128 rows x 80 B (32 bf16 + 8 pad -> conflict-free ldmatrix).
// ---------------------------------------------------------------------------
__global__ __launch_bounds__(256) void gemm_tc(
    const __nv_bfloat16* __restrict__ Ahi, const __nv_bfloat16* __restrict__ Alo,
    const __nv_bfloat16* __restrict__ Bhi, const __nv_bfloat16* __restrict__ Blo,
    const float* __restrict__ bias, float* __restrict__ C, float alpha)
{
    extern __shared__ __align__(128) char smem[];   // 2 * 40960 B
    const int tid  = threadIdx.x;
    const int lane = tid & 31;
    const int wid  = tid >> 5;
    const int wm   = wid >> 2;          // 0..1
    const int wn   = wid & 3;           // 0..3
    const int m0   = blockIdx.y * 128;
    const int n0   = blockIdx.x * 128;
    const uint32_t sbase = smem_to_u32(smem);

    float c[4][4][4];
#pragma unroll
    for (int i = 0; i < 4; i++)
#pragma unroll
        for (int j = 0; j < 4; j++)
#pragma unroll
            for (int q = 0; q < 4; q++) c[i][j][q] = 0.f;

    // ldmatrix per-lane address components
    const uint32_t arow  = lane & 15;
    const uint32_t ahalf = (uint32_t)(lane >> 4);          // 0/1 -> +16B (8 cols)
    const uint32_t brow  = (lane & 7) | (((uint32_t)lane >> 4) << 3);
    const uint32_t bhalf = ((uint32_t)lane >> 3) & 1;

    auto load_stage = [&](int chunk, int st) {
        const int kt = chunk * 32;
        const uint32_t dstb = sbase + st * 40960;
#pragma unroll
        for (int t = 0; t < 4; t++) {
            const __nv_bfloat16* src = (t == 0) ? Ahi : (t == 1) ? Alo : (t == 2) ? Bhi : Blo;
            const int gbase = (t < 2) ? m0 : n0;
#pragma unroll
            for (int i = 0; i < 2; i++) {
                int cid = i * 256 + tid;       // 0..511
                int row = cid >> 2;
                int kc  = cid & 3;             // 16B chunk
                cp16(dstb + t * 10240 + row * 80 + kc * 16,
                     src + (size_t)(gbase + row) * DMODEL + kt + kc * 8);
            }
        }
    };

    auto mma_all = [&](uint32_t (*ah)[4], uint32_t (*bb)[4]) {
#pragma unroll
        for (int i = 0; i < 4; i++)
#pragma unroll
            for (int j = 0; j < 4; j++)
                mma16816(c[i][j], ah[i], &bb[j >> 1][(j & 1) * 2]);
    };

    auto compute_stage = [&](int st) {
        const uint32_t tb = sbase + st * 40960;
#pragma unroll
        for (int kk = 0; kk < 2; kk++) {
            const uint32_t koff = kk * 32;     // 16 bf16 = 32 B
            uint32_t ah[4][4], bb[2][4];
            // pass 1: Ahi x Bhi
#pragma unroll
            for (int i = 0; i < 4; i++)
                ldsm4(ah[i], tb + (wm * 64 + i * 16 + arow) * 80 + koff + ahalf * 16);
#pragma unroll
            for (int j = 0; j < 2; j++)
                ldsm4(bb[j], tb + 20480 + (wn * 32 + j * 16 + brow) * 80 + koff + bhalf * 16);
            mma_all(ah, bb);
            // pass 2: Alo x Bhi
#pragma unroll
            for (int i = 0; i < 4; i++)
                ldsm4(ah[i], tb + 10240 + (wm * 64 + i * 16 + arow) * 80 + koff + ahalf * 16);
            mma_all(ah, bb);
            // pass 3: Ahi x Blo
#pragma unroll
            for (int i = 0; i < 4; i++)
                ldsm4(ah[i], tb + (wm * 64 + i * 16 + arow) * 80 + koff + ahalf * 16);
#pragma unroll
            for (int j = 0; j < 2; j++)
                ldsm4(bb[j], tb + 30720 + (wn * 32 + j * 16 + brow) * 80 + koff + bhalf * 16);
            mma_all(ah, bb);
        }
    };

    load_stage(0, 0);
    asm volatile("cp.async.commit_group;" ::: "memory");

    const int NK = DMODEL / 32;   // 32 chunks
    for (int ch = 0; ch < NK; ch++) {
        if (ch + 1 < NK) {
            load_stage(ch + 1, (ch + 1) & 1);
            asm volatile("cp.async.commit_group;" ::: "memory");
            asm volatile("cp.async.wait_group 1;" ::: "memory");
        } else {
            asm volatile("cp.async.wait_group 0;" ::: "memory");
        }
        __syncthreads();
        compute_stage(ch & 1);
        __syncthreads();
    }

    // Epilogue: bias + alpha, direct float2 stores
#pragma unroll
    for (int i = 0; i < 4; i++) {
        const int r = m0 + wm * 64 + i * 16 + (lane >> 2);
#pragma unroll
        for (int j = 0; j < 4; j++) {
            const int col = n0 + wn * 32 + j * 8 + (lane & 3) * 2;
            const float b0 = bias[col], b1 = bias[col + 1];
            float2 v0, v1;
            v0.x = alpha * (c[i][j][0] + b0); v0.y = alpha * (c[i][j][1] + b1);
            v1.x = alpha * (c[i][j][2] + b0); v1.y = alpha * (c[i][j][3] + b1);
            *(float2*)(C + (size_t)r * DMODEL + col)       = v0;
            *(float2*)(C + (size_t)(r + 8) * DMODEL + col) = v1;
        }
    }
}

// ---------------------------------------------------------------------------
// Flash-style causal attention (SIMT fp32) — proven in round 1.
// ---------------------------------------------------------------------------
__global__ __launch_bounds__(256) void attn_kernel(
    const float* __restrict__ Q, const float* __restrict__ K,
    const float* __restrict__ V, float* __restrict__ O)
{
    extern __shared__ float sm[];
    float* Qs = sm;
    float* Ks = sm + 64 * 64;
    float* Vs = Ks + 64 * 65;
    float* Ps = Vs + 64 * 64;

    const int qt = blockIdx.x;
    const int h  = blockIdx.y;
    const int b  = blockIdx.z;
    const int qbase = qt * 64;
    const int tid = threadIdx.x;
    const int tx = tid & 15;
    const int ty = tid >> 4;
    const size_t tokbase = (size_t)b * 2048;

#pragma unroll
    for (int p = 0; p < 4; p++) {
        int f = tid + p * 256;
        int row = f >> 4;
        int c = (f & 15) << 2;
        float4 v = *(const float4*)(Q + (tokbase + qbase + row) * DMODEL + h * HDIM + c);
        *(float4*)&Qs[row * 64 + c] = v;
    }

    float acc[4][4];
#pragma unroll
    for (int i = 0; i < 4; i++)
#pragma unroll
        for (int j = 0; j < 4; j++) acc[i][j] = 0.f;
    float mrow[4], lrow[4];
#pragma unroll
    for (int i = 0; i < 4; i++) { mrow[i] = -INFINITY; lrow[i] = 0.f; }

    __syncthreads();

    for (int kt = 0; kt <= qt; kt++) {
        const int kbase = kt * 64;
#pragma unroll
        for (int p = 0; p < 4; p++) {
            int f = tid + p * 256;
            int row = f >> 4;
            int c = (f & 15) << 2;
            float4 vk = *(const float4*)(K + (tokbase + kbase + row) * DMODEL + h * HDIM + c);
            Ks[row * 65 + c + 0] = vk.x; Ks[row * 65 + c + 1] = vk.y;
            Ks[row * 65 + c + 2] = vk.z; Ks[row * 65 + c + 3] = vk.w;
            float4 vv = *(const float4*)(V + (tokbase + kbase + row) * DMODEL + h * HDIM + c);
            *(float4*)&Vs[row * 64 + c] = vv;
        }
        __syncthreads();

        float s[4][4];
#pragma unroll
        for (int i = 0; i < 4; i++)
#pragma unroll
            for (int j = 0; j < 4; j++) s[i][j] = 0.f;

#pragma unroll 8
        for (int d = 0; d < 64; d++) {
            float a0 = Qs[(0 * 16 + ty) * 64 + d];
            float a1 = Qs[(1 * 16 + ty) * 64 + d];
            float a2 = Qs[(2 * 16 + ty) * 64 + d];
            float a3 = Qs[(3 * 16 + ty) * 64 + d];
            float b0 = Ks[(0 * 16 + tx) * 65 + d];
            float b1 = Ks[(1 * 16 + tx) * 65 + d];
            float b2 = Ks[(2 * 16 + tx) * 65 + d];
            float b3 = Ks[(3 * 16 + tx) * 65 + d];
            s[0][0] += a0 * b0; s[0][1] += a0 * b1; s[0][2] += a0 * b2; s[0][3] += a0 * b3;
            s[1][0] += a1 * b0; s[1][1] += a1 * b1; s[1][2] += a1 * b2; s[1][3] += a1 * b3;
            s[2][0] += a2 * b0; s[2][1] += a2 * b1; s[2][2] += a2 * b2; s[2][3] += a2 * b3;
            s[3][0] += a3 * b0; s[3][1] += a3 * b1; s[3][2] += a3 * b2; s[3][3] += a3 * b3;
        }

        if (kt == qt) {
#pragma unroll
            for (int i = 0; i < 4; i++)
#pragma unroll
                for (int j = 0; j < 4; j++)
                    if (j * 16 + tx > i * 16 + ty) s[i][j] = -INFINITY;
        }

#pragma unroll
        for (int i = 0; i < 4; i++) {
            float mt = fmaxf(fmaxf(s[i][0], s[i][1]), fmaxf(s[i][2], s[i][3]));
#pragma unroll
            for (int off = 1; off < 16; off <<= 1)
                mt = fmaxf(mt, __shfl_xor_sync(0xffffffffu, mt, off, 16));
            float mn = fmaxf(mrow[i], mt);
            float corr = __expf(mrow[i] - mn);
            mrow[i] = mn;
            float rs = 0.f;
#pragma unroll
            for (int j = 0; j < 4; j++) {
                float p = __expf(s[i][j] - mn);
                Ps[(i * 16 + ty) * 64 + j * 16 + tx] = p;
                rs += p;
            }
#pragma unroll
            for (int off = 1; off < 16; off <<= 1)
                rs += __shfl_xor_sync(0xffffffffu, rs, off, 16);
            lrow[i] = lrow[i] * corr + rs;
#pragma unroll
            for (int j = 0; j < 4; j++) acc[i][j] *= corr;
        }
        __syncwarp();

#pragma unroll 8
        for (int k = 0; k < 64; k++) {
            float p0 = Ps[(0 * 16 + ty) * 64 + k];
            float p1 = Ps[(1 * 16 + ty) * 64 + k];
            float p2 = Ps[(2 * 16 + ty) * 64 + k];
            float p3 = Ps[(3 * 16 + ty) * 64 + k];
            float v0 = Vs[k * 64 + 0 * 16 + tx];
            float v1 = Vs[k * 64 + 1 * 16 + tx];
            float v2 = Vs[k * 64 + 2 * 16 + tx];
            float v3 = Vs[k * 64 + 3 * 16 + tx];
            acc[0][0] += p0 * v0; acc[0][1] += p0 * v1; acc[0][2] += p0 * v2; acc[0][3] += p0 * v3;
            acc[1][0] += p1 * v0; acc[1][1] += p1 * v1; acc[1][2] += p1 * v2; acc[1][3] += p1 * v3;
            acc[2][0] += p2 * v0; acc[2][1] += p2 * v1; acc[2][2] += p2 * v2; acc[2][3] += p2 * v3;
            acc[3][0] += p3 * v0; acc[3][1] += p3 * v1; acc[3][2] += p3 * v2; acc[3][3] += p3 * v3;
        }
        __syncthreads();
    }

#pragma unroll
    for (int i = 0; i < 4; i++) {
        float inv = 1.f / lrow[i];
#pragma unroll
        for (int j = 0; j < 4; j++)
            O[(tokbase + qbase + i * 16 + ty) * DMODEL + h * HDIM + j * 16 + tx] =
                acc[i][j] * inv;
    }
}

// ---------------------------------------------------------------------------
// Residual add + LayerNorm
// ---------------------------------------------------------------------------
__global__ __launch_bounds__(256) void ln_kernel(
    const float* __restrict__ Osrc, const float* __restrict__ X,
    const float* __restrict__ g, const float* __restrict__ beta,
    float* __restrict__ out)
{
    const int row = blockIdx.x;
    const int tid = threadIdx.x;
    const float* o = Osrc + (size_t)row * DMODEL;
    const float* x = X + (size_t)row * DMODEL;

    float v[4];
    float s = 0.f, s2 = 0.f;
#pragma unroll
    for (int i = 0; i < 4; i++) {
        int c = tid + i * 256;
        float t = o[c] + x[c];
        v[i] = t; s += t; s2 += t * t;
    }
#pragma unroll
    for (int off = 16; off; off >>= 1) {
        s  += __shfl_xor_sync(0xffffffffu, s, off);
        s2 += __shfl_xor_sync(0xffffffffu, s2, off);
    }
    __shared__ float red[18];
    int w = tid >> 5;
    if ((tid & 31) == 0) { red[w] = s; red[8 + w] = s2; }
    __syncthreads();
    if (tid == 0) {
        float S = 0.f, S2 = 0.f;
        for (int k = 0; k < 8; k++) { S += red[k]; S2 += red[8 + k]; }
        red[16] = S; red[17] = S2;
    }
    __syncthreads();
    float mu   = red[16] * (1.f / 1024.f);
    float var  = red[17] * (1.f / 1024.f) - mu * mu;
    float rstd = rsqrtf(var + 1e-5f);
#pragma unroll
    for (int i = 0; i < 4; i++) {
        int c = tid + i * 256;
        out[(size_t)row * DMODEL + c] = (v[i] - mu) * rstd * g[c] + beta[c];
    }
}

// ---------------------------------------------------------------------------
extern "C" void kernel_launch(void* const* d_in, const int* in_sizes, int n_in,
                              void* d_out, int out_size)
{
    const float* X  = (const float*)d_in[0];
    const float* Wq = (const float*)d_in[1];
    const float* bq = (const float*)d_in[2];
    const float* Wk = (const float*)d_in[3];
    const float* bk = (const float*)d_in[4];
    const float* Wv = (const float*)d_in[5];
    const float* bv = (const float*)d_in[6];
    const float* Wo = (const float*)d_in[7];
    const float* bo = (const float*)d_in[8];
    const float* lg = (const float*)d_in[9];
    const float* lb = (const float*)d_in[10];
    float* out = (float*)d_out;

    float* f32 = nullptr;
    cudaGetSymbolAddress((void**)&f32, g_f32);
    float* Qb = f32 + (size_t)0 * M_TOK * DMODEL;
    float* Kb = f32 + (size_t)1 * M_TOK * DMODEL;
    float* Vb = f32 + (size_t)2 * M_TOK * DMODEL;
    float* Ab = f32 + (size_t)3 * M_TOK * DMODEL;
    float* Ob = f32 + (size_t)4 * M_TOK * DMODEL;

    __nv_bfloat16 *xhi, *xlo, *ahi, *alo, *whi, *wlo;
    cudaGetSymbolAddress((void**)&xhi, g_xhi);
    cudaGetSymbolAddress((void**)&xlo, g_xlo);
    cudaGetSymbolAddress((void**)&ahi, g_ahi);
    cudaGetSymbolAddress((void**)&alo, g_alo);
    cudaGetSymbolAddress((void**)&whi, g_whi);
    cudaGetSymbolAddress((void**)&wlo, g_wlo);

    const int NX4 = (M_TOK * DMODEL) / 4;       // 1,048,576
    const int NW4 = (DMODEL * DMODEL) / 4;      // 262,144
    const size_t WSTRIDE = (size_t)DMODEL * DMODEL;

    split_bf16<<<NX4 / 256, 256>>>(X, xhi, xlo, NX4);
    split_bf16<<<NW4 / 256, 256>>>(Wq, whi + 0 * WSTRIDE, wlo + 0 * WSTRIDE, NW4);
    split_bf16<<<NW4 / 256, 256>>>(Wk, whi + 1 * WSTRIDE, wlo + 1 * WSTRIDE, NW4);
    split_bf16<<<NW4 / 256, 256>>>(Wv, whi + 2 * WSTRIDE, wlo + 2 * WSTRIDE, NW4);
    split_bf16<<<NW4 / 256, 256>>>(Wo, whi + 3 * WSTRIDE, wlo + 3 * WSTRIDE, NW4);

    const int gemm_smem = 2 * 40960;            // 81,920 B
    cudaFuncSetAttribute(gemm_tc, cudaFuncAttributeMaxDynamicSharedMemorySize, gemm_smem);
    dim3 ggrid(DMODEL / 128, M_TOK / 128);      // (8, 32)

    const float scale = 0.125f;  // HD^-0.5
    gemm_tc<<<ggrid, 256, gemm_smem>>>(xhi, xlo, whi + 0 * WSTRIDE, wlo + 0 * WSTRIDE, bq, Qb, scale);
    gemm_tc<<<ggrid, 256, gemm_smem>>>(xhi, xlo, whi + 1 * WSTRIDE, wlo + 1 * WSTRIDE, bk, Kb, 1.f);
    gemm_tc<<<ggrid, 256, gemm_smem>>>(xhi, xlo, whi + 2 * WSTRIDE, wlo + 2 * WSTRIDE, bv, Vb, 1.f);

    const int attn_smem = (64 * 64 * 3 + 64 * 65) * (int)sizeof(float);
    cudaFuncSetAttribute(attn_kernel, cudaFuncAttributeMaxDynamicSharedMemorySize, attn_smem);
    attn_kernel<<<dim3(32, NHEAD, 2), 256, attn_smem>>>(Qb, Kb, Vb, Ab);

    split_bf16<<<NX4 / 256, 256>>>(Ab, ahi, alo, NX4);
    gemm_tc<<<ggrid, 256, gemm_smem>>>(ahi, alo, whi + 3 * WSTRIDE, wlo + 3 * WSTRIDE, bo, Ob, 1.f);

    ln_kernel<<<M_TOK, 256>>>(Ob, X, lg, lb, out);
}

// round 4
// speedup vs baseline: 2.5129x; 1.6217x over previous
#include <cuda_runtime.h>
#include <cuda_bf16.h>
#include <cstdint>
#include <math.h>

#define M_TOK 4096   // B*S
#define DMODEL 1024
#define NHEAD 16
#define HDIM 64

// fp32 scratch: only the O-projection output (LN input)
__device__ float g_ob[(size_t)M_TOK * DMODEL];
// bf16 hi/lo operands
__device__ __nv_bfloat16 g_xhi[(size_t)M_TOK * DMODEL], g_xlo[(size_t)M_TOK * DMODEL];
__device__ __nv_bfloat16 g_qh[(size_t)M_TOK * DMODEL], g_ql[(size_t)M_TOK * DMODEL];
__device__ __nv_bfloat16 g_kh[(size_t)M_TOK * DMODEL], g_kl[(size_t)M_TOK * DMODEL];
__device__ __nv_bfloat16 g_vh[(size_t)M_TOK * DMODEL], g_vl[(size_t)M_TOK * DMODEL];
__device__ __nv_bfloat16 g_ahi[(size_t)M_TOK * DMODEL], g_alo[(size_t)M_TOK * DMODEL];
__device__ __nv_bfloat16 g_whi[4][(size_t)DMODEL * DMODEL], g_wlo[4][(size_t)DMODEL * DMODEL];

// ---------------------------------------------------------------------------
// PTX helpers valid on base sm_103 target
// ---------------------------------------------------------------------------
__device__ __forceinline__ uint32_t smem_to_u32(const void* p) {
    uint32_t a;
    asm("{ .reg .u64 t; cvta.to.shared.u64 t, %1; cvt.u32.u64 %0, t; }" : "=r"(a) : "l"(p));
    return a;
}
__device__ __forceinline__ void cp16(uint32_t dst, const void* src) {
    asm volatile("cp.async.cg.shared.global [%0], [%1], 16;" :: "r"(dst), "l"(src));
}
__device__ __forceinline__ void ldsm4(uint32_t* r, uint32_t addr) {
    asm volatile("ldmatrix.sync.aligned.m8n8.x4.shared.b16 {%0,%1,%2,%3}, [%4];"
                 : "=r"(r[0]), "=r"(r[1]), "=r"(r[2]), "=r"(r[3]) : "r"(addr));
}
__device__ __forceinline__ void ldsm4t(uint32_t* r, uint32_t addr) {
    asm volatile("ldmatrix.sync.aligned.m8n8.x4.trans.shared.b16 {%0,%1,%2,%3}, [%4];"
                 : "=r"(r[0]), "=r"(r[1]), "=r"(r[2]), "=r"(r[3]) : "r"(addr));
}
__device__ __forceinline__ void mma16816(float* c, const uint32_t* a, const uint32_t* b) {
    asm volatile(
        "mma.sync.aligned.m16n8k16.row.col.f32.bf16.bf16.f32 "
        "{%0,%1,%2,%3}, {%4,%5,%6,%7}, {%8,%9}, {%0,%1,%2,%3};"
        : "+f"(c[0]), "+f"(c[1]), "+f"(c[2]), "+f"(c[3])
        : "r"(a[0]), "r"(a[1]), "r"(a[2]), "r"(a[3]), "r"(b[0]), "r"(b[1]));
}
// pack two floats to bf16x2 hi + lo-compensation pair
__device__ __forceinline__ void split2(float x, float y, uint32_t& hi, uint32_t& lo) {
    __nv_bfloat162 h = __floats2bfloat162_rn(x, y);
    float hx = __low2float(h), hy = __high2float(h);
    __nv_bfloat162 l = __floats2bfloat162_rn(x - hx, y - hy);
    hi = *reinterpret_cast<uint32_t*>(&h);
    lo = *reinterpret_cast<uint32_t*>(&l);
}

// ---------------------------------------------------------------------------
// fp32 -> bf16 hi/lo split (for X and the weights)
// ---------------------------------------------------------------------------
__global__ __launch_bounds__(256) void split_bf16(
    const float* __restrict__ x, __nv_bfloat16* __restrict__ hi,
    __nv_bfloat16* __restrict__ lo, int n4)
{
    int i = blockIdx.x * 256 + threadIdx.x;
    if (i >= n4) return;
    float4 v = *(const float4*)(x + (size_t)i * 4);
    uint32_t h0, l0, h1, l1;
    split2(v.x, v.y, h0, l0);
    split2(v.z, v.w, h1, l1);
    uint32_t* hp = (uint32_t*)(hi + (size_t)i * 4);
    uint32_t* lp = (uint32_t*)(lo + (size_t)i * 4);
    hp[0] = h0; hp[1] = h1;
    lp[0] = l0; lp[1] = l1;
}

// ---------------------------------------------------------------------------
// HMMA NT GEMM, bf16 hi/lo 3-pass. Output either fp32 (Cf) or split bf16
// (Chi/Clo, when Chi != nullptr).
// ---------------------------------------------------------------------------
__global__ __launch_bounds__(256) void gemm_tc(
    const __nv_bfloat16* __restrict__ Ahi, const __nv_bfloat16* __restrict__ Alo,
    const __nv_bfloat16* __restrict__ Bhi, const __nv_bfloat16* __restrict__ Blo,
    const float* __restrict__ bias, float* __restrict__ Cf,
    __nv_bfloat16* __restrict__ Chi, __nv_bfloat16* __restrict__ Clo, float alpha)
{
    extern __shared__ __align__(128) char smem[];   // 2 * 40960 B
    const int tid  = threadIdx.x;
    const int lane = tid & 31;
    const int wid  = tid >> 5;
    const int wm   = wid >> 2;
    const int wn   = wid & 3;
    const int m0   = blockIdx.y * 128;
    const int n0   = blockIdx.x * 128;
    const uint32_t sbase = smem_to_u32(smem);

    float c[4][4][4];
#pragma unroll
    for (int i = 0; i < 4; i++)
#pragma unroll
        for (int j = 0; j < 4; j++)
#pragma unroll
            for (int q = 0; q < 4; q++) c[i][j][q] = 0.f;

    const uint32_t arow  = lane & 15;
    const uint32_t ahalf = (uint32_t)(lane >> 4);
    const uint32_t brow  = (lane & 7) | (((uint32_t)lane >> 4) << 3);
    const uint32_t bhalf = ((uint32_t)lane >> 3) & 1;

    auto load_stage = [&](int chunk, int st) {
        const int kt = chunk * 32;
        const uint32_t dstb = sbase + st * 40960;
#pragma unroll
        for (int t = 0; t < 4; t++) {
            const __nv_bfloat16* src = (t == 0) ? Ahi : (t == 1) ? Alo : (t == 2) ? Bhi : Blo;
            const int gbase = (t < 2) ? m0 : n0;
#pragma unroll
            for (int i = 0; i < 2; i++) {
                int cid = i * 256 + tid;
                int row = cid >> 2;
                int kc  = cid & 3;
                cp16(dstb + t * 10240 + row * 80 + kc * 16,
                     src + (size_t)(gbase + row) * DMODEL + kt + kc * 8);
            }
        }
    };

    auto mma_all = [&](uint32_t (*ah)[4], uint32_t (*bb)[4]) {
#pragma unroll
        for (int i = 0; i < 4; i++)
#pragma unroll
            for (int j = 0; j < 4; j++)
                mma16816(c[i][j], ah[i], &bb[j >> 1][(j & 1) * 2]);
    };

    auto compute_stage = [&](int st) {
        const uint32_t tb = sbase + st * 40960;
#pragma unroll
        for (int kk = 0; kk < 2; kk++) {
            const uint32_t koff = kk * 32;
            uint32_t ah[4][4], bb[2][4];
#pragma unroll
            for (int i = 0; i < 4; i++)
                ldsm4(ah[i], tb + (wm * 64 + i * 16 + arow) * 80 + koff + ahalf * 16);
#pragma unroll
            for (int j = 0; j < 2; j++)
                ldsm4(bb[j], tb + 20480 + (wn * 32 + j * 16 + brow) * 80 + koff + bhalf * 16);
            mma_all(ah, bb);
#pragma unroll
            for (int i = 0; i < 4; i++)
                ldsm4(ah[i], tb + 10240 + (wm * 64 + i * 16 + arow) * 80 + koff + ahalf * 16);
            mma_all(ah, bb);
#pragma unroll
            for (int i = 0; i < 4; i++)
                ldsm4(ah[i], tb + (wm * 64 + i * 16 + arow) * 80 + koff + ahalf * 16);
#pragma unroll
            for (int j = 0; j < 2; j++)
                ldsm4(bb[j], tb + 30720 + (wn * 32 + j * 16 + brow) * 80 + koff + bhalf * 16);
            mma_all(ah, bb);
        }
    };

    load_stage(0, 0);
    asm volatile("cp.async.commit_group;" ::: "memory");

    const int NK = DMODEL / 32;
    for (int ch = 0; ch < NK; ch++) {
        if (ch + 1 < NK) {
            load_stage(ch + 1, (ch + 1) & 1);
            asm volatile("cp.async.commit_group;" ::: "memory");
            asm volatile("cp.async.wait_group 1;" ::: "memory");
        } else {
            asm volatile("cp.async.wait_group 0;" ::: "memory");
        }
        __syncthreads();
        compute_stage(ch & 1);
        __syncthreads();
    }

#pragma unroll
    for (int i = 0; i < 4; i++) {
        const int r = m0 + wm * 64 + i * 16 + (lane >> 2);
#pragma unroll
        for (int j = 0; j < 4; j++) {
            const int col = n0 + wn * 32 + j * 8 + (lane & 3) * 2;
            const float b0 = bias[col], b1 = bias[col + 1];
            float v00 = alpha * (c[i][j][0] + b0), v01 = alpha * (c[i][j][1] + b1);
            float v10 = alpha * (c[i][j][2] + b0), v11 = alpha * (c[i][j][3] + b1);
            if (Chi) {
                uint32_t h, l;
                split2(v00, v01, h, l);
                *(uint32_t*)(Chi + (size_t)r * DMODEL + col) = h;
                *(uint32_t*)(Clo + (size_t)r * DMODEL + col) = l;
                split2(v10, v11, h, l);
                *(uint32_t*)(Chi + (size_t)(r + 8) * DMODEL + col) = h;
                *(uint32_t*)(Clo + (size_t)(r + 8) * DMODEL + col) = l;
            } else {
                float2 w0, w1;
                w0.x = v00; w0.y = v01; w1.x = v10; w1.y = v11;
                *(float2*)(Cf + (size_t)r * DMODEL + col)       = w0;
                *(float2*)(Cf + (size_t)(r + 8) * DMODEL + col) = w1;
            }
        }
    }
}

// ---------------------------------------------------------------------------
// HMMA flash attention, causal. CTA = (qtile 64, head, batch), 128 threads.
// S = Q K^T and O += P V on tensor cores, 3 hi/lo passes each.
// smem (92160 B): Qhi@0 Qlo@9216; stage s at 18432+s*36864: Khi,Klo,Vhi,Vlo
// (9216 B each, 64 rows x 144 B padded stride).
// ---------------------------------------------------------------------------
__global__ __launch_bounds__(128) void attn_tc(
    const __nv_bfloat16* __restrict__ Qhi, const __nv_bfloat16* __restrict__ Qlo,
    const __nv_bfloat16* __restrict__ Khi, const __nv_bfloat16* __restrict__ Klo,
    const __nv_bfloat16* __restrict__ Vhi, const __nv_bfloat16* __restrict__ Vlo,
    __nv_bfloat16* __restrict__ Ohi, __nv_bfloat16* __restrict__ Olo)
{
    extern __shared__ __align__(128) char smem[];
    const uint32_t sb = smem_to_u32(smem);
    const int tid = threadIdx.x, lane = tid & 31, w = tid >> 5;
    const int qt = 31 - blockIdx.x;      // heavy tiles first
    const int h  = blockIdx.y;
    const int b  = blockIdx.z;
    const size_t tokq = (size_t)b * 2048 + qt * 64;
    const size_t hoff = (size_t)h * HDIM;

    // Q load (hi+lo)
#pragma unroll
    for (int i = 0; i < 8; i++) {
        int c = tid + i * 128;
        int t = c >> 9, r = (c >> 3) & 63, kc = c & 7;
        const __nv_bfloat16* src = t ? Qlo : Qhi;
        cp16(sb + t * 9216 + r * 144 + kc * 16, src + (tokq + r) * DMODEL + hoff + kc * 8);
    }
    auto load_kv = [&](int kt, int s) {
        const size_t tokk = (size_t)b * 2048 + kt * 64;
        const uint32_t db = sb + 18432 + s * 36864;
#pragma unroll
        for (int i = 0; i < 16; i++) {
            int c = tid + i * 128;
            int t = c >> 9, r = (c >> 3) & 63, kc = c & 7;
            const __nv_bfloat16* src = (t == 0) ? Khi : (t == 1) ? Klo : (t == 2) ? Vhi : Vlo;
            cp16(db + t * 9216 + r * 144 + kc * 16, src + (tokk + r) * DMODEL + hoff + kc * 8);
        }
    };
    load_kv(0, 0);
    asm volatile("cp.async.commit_group;" ::: "memory");

    float o[8][4];
#pragma unroll
    for (int nb = 0; nb < 8; nb++)
#pragma unroll
        for (int q = 0; q < 4; q++) o[nb][q] = 0.f;
    float m0 = -INFINITY, m1 = -INFINITY, l0 = 0.f, l1 = 0.f;

    // per-lane ldmatrix address components
    const uint32_t qa  = (uint32_t)((w * 16 + (lane & 15)) * 144 + (lane >> 4) * 16);
    const uint32_t kbr = (uint32_t)((lane & 7) | ((lane >> 4) << 3));
    const uint32_t kbh = (uint32_t)(((lane >> 3) & 1) * 16);
    const uint32_t vkr = (uint32_t)((lane & 7) + ((lane >> 3) & 1) * 8);
    const uint32_t vnc = (uint32_t)(((lane >> 4) & 1) * 8);

    for (int kt = 0; kt <= qt; kt++) {
        if (kt < qt) {
            load_kv(kt + 1, (kt + 1) & 1);
            asm volatile("cp.async.commit_group;" ::: "memory");
            asm volatile("cp.async.wait_group 1;" ::: "memory");
        } else {
            asm volatile("cp.async.wait_group 0;" ::: "memory");
        }
        __syncthreads();
        const uint32_t stb = sb + 18432 + (kt & 1) * 36864;
        const uint32_t KHB = stb, KLB = stb + 9216, VHB = stb + 18432, VLB = stb + 27648;

        // ---- S = Q K^T (3 passes) ----
        float sfr[8][4];
#pragma unroll
        for (int nb = 0; nb < 8; nb++)
#pragma unroll
            for (int q = 0; q < 4; q++) sfr[nb][q] = 0.f;

#pragma unroll
        for (int kk = 0; kk < 4; kk++) {
            uint32_t ah[4], al[4], bh[4][4], bl[4][4];
            ldsm4(ah, sb + qa + kk * 32);
            ldsm4(al, sb + 9216 + qa + kk * 32);
#pragma unroll
            for (int t = 0; t < 4; t++) {
                ldsm4(bh[t], KHB + (t * 16 + kbr) * 144 + kk * 32 + kbh);
                ldsm4(bl[t], KLB + (t * 16 + kbr) * 144 + kk * 32 + kbh);
            }
#pragma unroll
            for (int nb = 0; nb < 8; nb++) {
                uint32_t* ph = &bh[nb >> 1][(nb & 1) * 2];
                uint32_t* pl = &bl[nb >> 1][(nb & 1) * 2];
                mma16816(sfr[nb], ah, ph);
                mma16816(sfr[nb], al, ph);
                mma16816(sfr[nb], ah, pl);
            }
        }

        // causal mask on the diagonal tile
        if (kt == qt) {
            const int r0 = w * 16 + (lane >> 2), r1 = r0 + 8;
#pragma unroll
            for (int nb = 0; nb < 8; nb++) {
                const int cc = nb * 8 + (lane & 3) * 2;
                if (cc     > r0) sfr[nb][0] = -INFINITY;
                if (cc + 1 > r0) sfr[nb][1] = -INFINITY;
                if (cc     > r1) sfr[nb][2] = -INFINITY;
                if (cc + 1 > r1) sfr[nb][3] = -INFINITY;
            }
        }

        // ---- online softmax (rows shared by lane quads) ----
        float rm0 = -INFINITY, rm1 = -INFINITY;
#pragma unroll
        for (int nb = 0; nb < 8; nb++) {
            rm0 = fmaxf(rm0, fmaxf(sfr[nb][0], sfr[nb][1]));
            rm1 = fmaxf(rm1, fmaxf(sfr[nb][2], sfr[nb][3]));
        }
        rm0 = fmaxf(rm0, __shfl_xor_sync(0xffffffffu, rm0, 1));
        rm0 = fmaxf(rm0, __shfl_xor_sync(0xffffffffu, rm0, 2));
        rm1 = fmaxf(rm1, __shfl_xor_sync(0xffffffffu, rm1, 1));
        rm1 = fmaxf(rm1, __shfl_xor_sync(0xffffffffu, rm1, 2));
        float nm0 = fmaxf(m0, rm0), nm1 = fmaxf(m1, rm1);
        float c0 = __expf(m0 - nm0), c1 = __expf(m1 - nm1);
        m0 = nm0; m1 = nm1;
        float rs0 = 0.f, rs1 = 0.f;
#pragma unroll
        for (int nb = 0; nb < 8; nb++) {
            sfr[nb][0] = __expf(sfr[nb][0] - m0); rs0 += sfr[nb][0];
            sfr[nb][1] = __expf(sfr[nb][1] - m0); rs0 += sfr[nb][1];
            sfr[nb][2] = __expf(sfr[nb][2] - m1); rs1 += sfr[nb][2];
            sfr[nb][3] = __expf(sfr[nb][3] - m1); rs1 += sfr[nb][3];
        }
        rs0 += __shfl_xor_sync(0xffffffffu, rs0, 1);
        rs0 += __shfl_xor_sync(0xffffffffu, rs0, 2);
        rs1 += __shfl_xor_sync(0xffffffffu, rs1, 1);
        rs1 += __shfl_xor_sync(0xffffffffu, rs1, 2);
        l0 = l0 * c0 + rs0;
        l1 = l1 * c1 + rs1;
#pragma unroll
        for (int nb = 0; nb < 8; nb++) {
            o[nb][0] *= c0; o[nb][1] *= c0; o[nb][2] *= c1; o[nb][3] *= c1;
        }

        // ---- O += P V (3 passes), P packed from registers ----
#pragma unroll
        for (int kk = 0; kk < 4; kk++) {
            uint32_t aph[4], apl[4];
            split2(sfr[2 * kk][0],     sfr[2 * kk][1],     aph[0], apl[0]);
            split2(sfr[2 * kk][2],     sfr[2 * kk][3],     aph[1], apl[1]);
            split2(sfr[2 * kk + 1][0], sfr[2 * kk + 1][1], aph[2], apl[2]);
            split2(sfr[2 * kk + 1][2], sfr[2 * kk + 1][3], aph[3], apl[3]);
            uint32_t vh[4][4], vl[4][4];
#pragma unroll
            for (int t = 0; t < 4; t++) {
                ldsm4t(vh[t], VHB + (kk * 16 + vkr) * 144 + (t * 16 + vnc) * 2);
                ldsm4t(vl[t], VLB + (kk * 16 + vkr) * 144 + (t * 16 + vnc) * 2);
            }
#pragma unroll
            for (int nb = 0; nb < 8; nb++) {
                uint32_t* ph = &vh[nb >> 1][(nb & 1) * 2];
                uint32_t* pl = &vl[nb >> 1][(nb & 1) * 2];
                mma16816(o[nb], aph, ph);
                mma16816(o[nb], apl, ph);
                mma16816(o[nb], aph, pl);
            }
        }
        __syncthreads();
    }

    // ---- epilogue: normalize, split, store ----
    const float i0 = 1.f / l0, i1 = 1.f / l1;
    const size_t r0 = tokq + w * 16 + (lane >> 2);
    const size_t r1 = r0 + 8;
#pragma unroll
    for (int nb = 0; nb < 8; nb++) {
        const size_t col = hoff + nb * 8 + (lane & 3) * 2;
        uint32_t hh, ll;
        split2(o[nb][0] * i0, o[nb][1] * i0, hh, ll);
        *(uint32_t*)(Ohi + r0 * DMODEL + col) = hh;
        *(uint32_t*)(Olo + r0 * DMODEL + col) = ll;
        split2(o[nb][2] * i1, o[nb][3] * i1, hh, ll);
        *(uint32_t*)(Ohi + r1 * DMODEL + col) = hh;
        *(uint32_t*)(Olo + r1 * DMODEL + col) = ll;
    }
}

// ---------------------------------------------------------------------------
// Residual add + LayerNorm
// ---------------------------------------------------------------------------
__global__ __launch_bounds__(256) void ln_kernel(
    const float* __restrict__ Osrc, const float* __restrict__ X,
    const float* __restrict__ g, const float* __restrict__ beta,
    float* __restrict__ out)
{
    const int row = blockIdx.x;
    const int tid = threadIdx.x;
    const float* o = Osrc + (size_t)row * DMODEL;
    const float* x = X + (size_t)row * DMODEL;

    float v[4];
    float s = 0.f, s2 = 0.f;
#pragma unroll
    for (int i = 0; i < 4; i++) {
        int c = tid + i * 256;
        float t = o[c] + x[c];
        v[i] = t; s += t; s2 += t * t;
    }
#pragma unroll
    for (int off = 16; off; off >>= 1) {
        s  += __shfl_xor_sync(0xffffffffu, s, off);
        s2 += __shfl_xor_sync(0xffffffffu, s2, off);
    }
    __shared__ float red[18];
    int w = tid >> 5;
    if ((tid & 31) == 0) { red[w] = s; red[8 + w] = s2; }
    __syncthreads();
    if (tid == 0) {
        float S = 0.f, S2 = 0.f;
        for (int k = 0; k < 8; k++) { S += red[k]; S2 += red[8 + k]; }
        red[16] = S; red[17] = S2;
    }
    __syncthreads();
    float mu   = red[16] * (1.f / 1024.f);
    float var  = red[17] * (1.f / 1024.f) - mu * mu;
    float rstd = rsqrtf(var + 1e-5f);
#pragma unroll
    for (int i = 0; i < 4; i++) {
        int c = tid + i * 256;
        out[(size_t)row * DMODEL + c] = (v[i] - mu) * rstd * g[c] + beta[c];
    }
}

// ---------------------------------------------------------------------------
extern "C" void kernel_launch(void* const* d_in, const int* in_sizes, int n_in,
                              void* d_out, int out_size)
{
    const float* X  = (const float*)d_in[0];
    const float* Wq = (const float*)d_in[1];
    const float* bq = (const float*)d_in[2];
    const float* Wk = (const float*)d_in[3];
    const float* bk = (const float*)d_in[4];
    const float* Wv = (const float*)d_in[5];
    const float* bv = (const float*)d_in[6];
    const float* Wo = (const float*)d_in[7];
    const float* bo = (const float*)d_in[8];
    const float* lg = (const float*)d_in[9];
    const float* lb = (const float*)d_in[10];
    float* out = (float*)d_out;

    float* Ob = nullptr;
    cudaGetSymbolAddress((void**)&Ob, g_ob);
    __nv_bfloat16 *xhi, *xlo, *qh, *ql, *kh, *kl, *vh, *vl, *ahi, *alo, *whi, *wlo;
    cudaGetSymbolAddress((void**)&xhi, g_xhi);
    cudaGetSymbolAddress((void**)&xlo, g_xlo);
    cudaGetSymbolAddress((void**)&qh, g_qh);
    cudaGetSymbolAddress((void**)&ql, g_ql);
    cudaGetSymbolAddress((void**)&kh, g_kh);
    cudaGetSymbolAddress((void**)&kl, g_kl);
    cudaGetSymbolAddress((void**)&vh, g_vh);
    cudaGetSymbolAddress((void**)&vl, g_vl);
    cudaGetSymbolAddress((void**)&ahi, g_ahi);
    cudaGetSymbolAddress((void**)&alo, g_alo);
    cudaGetSymbolAddress((void**)&whi, g_whi);
    cudaGetSymbolAddress((void**)&wlo, g_wlo);

    const int NX4 = (M_TOK * DMODEL) / 4;
    const int NW4 = (DMODEL * DMODEL) / 4;
    const size_t WS = (size_t)DMODEL * DMODEL;

    split_bf16<<<NX4 / 256, 256>>>(X, xhi, xlo, NX4);
    split_bf16<<<NW4 / 256, 256>>>(Wq, whi + 0 * WS, wlo + 0 * WS, NW4);
    split_bf16<<<NW4 / 256, 256>>>(Wk, whi + 1 * WS, wlo + 1 * WS, NW4);
    split_bf16<<<NW4 / 256, 256>>>(Wv, whi + 2 * WS, wlo + 2 * WS, NW4);
    split_bf16<<<NW4 / 256, 256>>>(Wo, whi + 3 * WS, wlo + 3 * WS, NW4);

    const int gemm_smem = 2 * 40960;
    cudaFuncSetAttribute(gemm_tc, cudaFuncAttributeMaxDynamicSharedMemorySize, gemm_smem);
    dim3 ggrid(DMODEL / 128, M_TOK / 128);

    const float scale = 0.125f;  // HD^-0.5
    gemm_tc<<<ggrid, 256, gemm_smem>>>(xhi, xlo, whi + 0 * WS, wlo + 0 * WS, bq, nullptr, qh, ql, scale);
    gemm_tc<<<ggrid, 256, gemm_smem>>>(xhi, xlo, whi + 1 * WS, wlo + 1 * WS, bk, nullptr, kh, kl, 1.f);
    gemm_tc<<<ggrid, 256, gemm_smem>>>(xhi, xlo, whi + 2 * WS, wlo + 2 * WS, bv, nullptr, vh, vl, 1.f);

    const int attn_smem = 18432 + 2 * 36864;    // 92160 B
    cudaFuncSetAttribute(attn_tc, cudaFuncAttributeMaxDynamicSharedMemorySize, attn_smem);
    attn_tc<<<dim3(32, NHEAD, 2), 128, attn_smem>>>(qh, ql, kh, kl, vh, vl, ahi, alo);

    gemm_tc<<<ggrid, 256, gemm_smem>>>(ahi, alo, whi + 3 * WS, wlo + 3 * WS, bo, Ob, nullptr, nullptr, 1.f);

    ln_kernel<<<M_TOK, 256>>>(Ob, X, lg, lb, out);
}

// round 5
// speedup vs baseline: 5.8729x; 2.3371x over previous
#include <cuda_runtime.h>
#include <cuda_fp16.h>
#include <cstdint>
#include <math.h>

#define M_TOK 4096   // B*S
#define DMODEL 1024
#define NHEAD 16
#define HDIM 64

// fp32 scratch for the LN input
__device__ float g_ob[(size_t)M_TOK * DMODEL];
// fp16 operands
__device__ __half g_xf[(size_t)M_TOK * DMODEL];
__device__ __half g_qf[(size_t)M_TOK * DMODEL], g_kf[(size_t)M_TOK * DMODEL];
__device__ __half g_vf[(size_t)M_TOK * DMODEL], g_af[(size_t)M_TOK * DMODEL];
__device__ __half g_wf[4][(size_t)DMODEL * DMODEL];

// ---------------------------------------------------------------------------
// PTX helpers valid on base sm_103 target
// ---------------------------------------------------------------------------
__device__ __forceinline__ uint32_t smem_to_u32(const void* p) {
    uint32_t a;
    asm("{ .reg .u64 t; cvta.to.shared.u64 t, %1; cvt.u32.u64 %0, t; }" : "=r"(a) : "l"(p));
    return a;
}
__device__ __forceinline__ void cp16(uint32_t dst, const void* src) {
    asm volatile("cp.async.cg.shared.global [%0], [%1], 16;" :: "r"(dst), "l"(src));
}
__device__ __forceinline__ void ldsm4(uint32_t* r, uint32_t addr) {
    asm volatile("ldmatrix.sync.aligned.m8n8.x4.shared.b16 {%0,%1,%2,%3}, [%4];"
                 : "=r"(r[0]), "=r"(r[1]), "=r"(r[2]), "=r"(r[3]) : "r"(addr));
}
__device__ __forceinline__ void ldsm4t(uint32_t* r, uint32_t addr) {
    asm volatile("ldmatrix.sync.aligned.m8n8.x4.trans.shared.b16 {%0,%1,%2,%3}, [%4];"
                 : "=r"(r[0]), "=r"(r[1]), "=r"(r[2]), "=r"(r[3]) : "r"(addr));
}
__device__ __forceinline__ void mma16816(float* c, const uint32_t* a, const uint32_t* b) {
    asm volatile(
        "mma.sync.aligned.m16n8k16.row.col.f32.f16.f16.f32 "
        "{%0,%1,%2,%3}, {%4,%5,%6,%7}, {%8,%9}, {%0,%1,%2,%3};"
        : "+f"(c[0]), "+f"(c[1]), "+f"(c[2]), "+f"(c[3])
        : "r"(a[0]), "r"(a[1]), "r"(a[2]), "r"(a[3]), "r"(b[0]), "r"(b[1]));
}
__device__ __forceinline__ uint32_t pack_h2(float x, float y) {
    __half2 h = __floats2half2_rn(x, y);
    return *reinterpret_cast<uint32_t*>(&h);
}

// ---------------------------------------------------------------------------
// fp32 -> fp16 convert
// ---------------------------------------------------------------------------
__global__ __launch_bounds__(256) void to_f16(
    const float* __restrict__ x, __half* __restrict__ y, int n4)
{
    int i = blockIdx.x * 256 + threadIdx.x;
    if (i >= n4) return;
    float4 v = *(const float4*)(x + (size_t)i * 4);
    uint2 o;
    o.x = pack_h2(v.x, v.y);
    o.y = pack_h2(v.z, v.w);
    *(uint2*)(y + (size_t)i * 4) = o;
}

// ---------------------------------------------------------------------------
// fp16 HMMA NT GEMM (single pass).
// C[m,n] = alpha * (sum_k A[m,k]*B[n,k] + bias[n]).  M=4096, N=1024, K=1024.
// CTA: 128x128 tile, BK=32, 256 threads (8 warps 2x4), warp tile 64x32.
// smem stage (20480 B): A@0, B@10240; rows 80 B (64 B data + 16 pad).
// Output fp32 (Cf) or fp16 (Ch) when Ch != nullptr.
// ---------------------------------------------------------------------------
__global__ __launch_bounds__(256) void gemm_tc(
    const __half* __restrict__ A, const __half* __restrict__ B,
    const float* __restrict__ bias, float* __restrict__ Cf,
    __half* __restrict__ Ch, float alpha)
{
    extern __shared__ __align__(128) char smem[];   // 2 * 20480 B
    const int tid  = threadIdx.x;
    const int lane = tid & 31;
    const int wid  = tid >> 5;
    const int wm   = wid >> 2;
    const int wn   = wid & 3;
    const int m0   = blockIdx.y * 128;
    const int n0   = blockIdx.x * 128;
    const uint32_t sbase = smem_to_u32(smem);

    float c[4][4][4];
#pragma unroll
    for (int i = 0; i < 4; i++)
#pragma unroll
        for (int j = 0; j < 4; j++)
#pragma unroll
            for (int q = 0; q < 4; q++) c[i][j][q] = 0.f;

    const uint32_t arow  = lane & 15;
    const uint32_t ahalf = (uint32_t)(lane >> 4);
    const uint32_t brow  = (lane & 7) | (((uint32_t)lane >> 4) << 3);
    const uint32_t bhalf = ((uint32_t)lane >> 3) & 1;

    auto load_stage = [&](int chunk, int st) {
        const int kt = chunk * 32;
        const uint32_t dstb = sbase + st * 20480;
        // 1024 cp16 over 256 threads: 4 each
#pragma unroll
        for (int i = 0; i < 4; i++) {
            int cid = i * 256 + tid;            // 0..1023
            int t   = cid >> 9;                 // 0:A 1:B
            int row = (cid >> 2) & 127;
            int kc  = cid & 3;
            const __half* src = t ? B : A;
            const int gbase = t ? n0 : m0;
            cp16(dstb + t * 10240 + row * 80 + kc * 16,
                 src + (size_t)(gbase + row) * DMODEL + kt + kc * 8);
        }
    };

    auto compute_stage = [&](int st) {
        const uint32_t tb = sbase + st * 20480;
#pragma unroll
        for (int kk = 0; kk < 2; kk++) {
            const uint32_t koff = kk * 32;
            uint32_t ah[4][4], bb[2][4];
#pragma unroll
            for (int i = 0; i < 4; i++)
                ldsm4(ah[i], tb + (wm * 64 + i * 16 + arow) * 80 + koff + ahalf * 16);
#pragma unroll
            for (int j = 0; j < 2; j++)
                ldsm4(bb[j], tb + 10240 + (wn * 32 + j * 16 + brow) * 80 + koff + bhalf * 16);
#pragma unroll
            for (int i = 0; i < 4; i++)
#pragma unroll
                for (int j = 0; j < 4; j++)
                    mma16816(c[i][j], ah[i], &bb[j >> 1][(j & 1) * 2]);
        }
    };

    load_stage(0, 0);
    asm volatile("cp.async.commit_group;" ::: "memory");

    const int NK = DMODEL / 32;
    for (int ch = 0; ch < NK; ch++) {
        if (ch + 1 < NK) {
            load_stage(ch + 1, (ch + 1) & 1);
            asm volatile("cp.async.commit_group;" ::: "memory");
            asm volatile("cp.async.wait_group 1;" ::: "memory");
        } else {
            asm volatile("cp.async.wait_group 0;" ::: "memory");
        }
        __syncthreads();
        compute_stage(ch & 1);
        __syncthreads();
    }

#pragma unroll
    for (int i = 0; i < 4; i++) {
        const int r = m0 + wm * 64 + i * 16 + (lane >> 2);
#pragma unroll
        for (int j = 0; j < 4; j++) {
            const int col = n0 + wn * 32 + j * 8 + (lane & 3) * 2;
            const float b0 = bias[col], b1 = bias[col + 1];
            float v00 = alpha * (c[i][j][0] + b0), v01 = alpha * (c[i][j][1] + b1);
            float v10 = alpha * (c[i][j][2] + b0), v11 = alpha * (c[i][j][3] + b1);
            if (Ch) {
                *(uint32_t*)(Ch + (size_t)r * DMODEL + col)       = pack_h2(v00, v01);
                *(uint32_t*)(Ch + (size_t)(r + 8) * DMODEL + col) = pack_h2(v10, v11);
            } else {
                float2 w0, w1;
                w0.x = v00; w0.y = v01; w1.x = v10; w1.y = v11;
                *(float2*)(Cf + (size_t)r * DMODEL + col)       = w0;
                *(float2*)(Cf + (size_t)(r + 8) * DMODEL + col) = w1;
            }
        }
    }
}

// ---------------------------------------------------------------------------
// fp16 HMMA flash attention, causal. CTA = (64-q tile, head, batch), 128 thr.
// smem (46080 B): Q@0 (9216); stage s at 9216 + s*18432: K@+0, V@+9216.
// Rows 144 B (128 B data + 16 pad).
// ---------------------------------------------------------------------------
__global__ __launch_bounds__(128) void attn_tc(
    const __half* __restrict__ Q, const __half* __restrict__ K,
    const __half* __restrict__ V, __half* __restrict__ O)
{
    extern __shared__ __align__(128) char smem[];
    const uint32_t sb = smem_to_u32(smem);
    const int tid = threadIdx.x, lane = tid & 31, w = tid >> 5;
    const int qt = 31 - blockIdx.x;      // heavy tiles first
    const int h  = blockIdx.y;
    const int b  = blockIdx.z;
    const size_t tokq = (size_t)b * 2048 + qt * 64;
    const size_t hoff = (size_t)h * HDIM;

    // Q tile: 64 rows x 128 B = 512 cp16, 4 per thread
#pragma unroll
    for (int i = 0; i < 4; i++) {
        int c = tid + i * 128;
        int r = c >> 3, kc = c & 7;
        cp16(sb + r * 144 + kc * 16, Q + (tokq + r) * DMODEL + hoff + kc * 8);
    }
    auto load_kv = [&](int kt, int s) {
        const size_t tokk = (size_t)b * 2048 + kt * 64;
        const uint32_t db = sb + 9216 + s * 18432;
#pragma unroll
        for (int i = 0; i < 8; i++) {
            int c = tid + i * 128;
            int t = c >> 9, r = (c >> 3) & 63, kc = c & 7;
            const __half* src = t ? V : K;
            cp16(db + t * 9216 + r * 144 + kc * 16, src + (tokk + r) * DMODEL + hoff + kc * 8);
        }
    };
    load_kv(0, 0);
    asm volatile("cp.async.commit_group;" ::: "memory");

    float o[8][4];
#pragma unroll
    for (int nb = 0; nb < 8; nb++)
#pragma unroll
        for (int q = 0; q < 4; q++) o[nb][q] = 0.f;
    float m0 = -INFINITY, m1 = -INFINITY, l0 = 0.f, l1 = 0.f;

    const uint32_t qa  = (uint32_t)((w * 16 + (lane & 15)) * 144 + (lane >> 4) * 16);
    const uint32_t kbr = (uint32_t)((lane & 7) | ((lane >> 4) << 3));
    const uint32_t kbh = (uint32_t)(((lane >> 3) & 1) * 16);
    const uint32_t vkr = (uint32_t)((lane & 7) + ((lane >> 3) & 1) * 8);
    const uint32_t vnc = (uint32_t)(((lane >> 4) & 1) * 8);

    for (int kt = 0; kt <= qt; kt++) {
        if (kt < qt) {
            load_kv(kt + 1, (kt + 1) & 1);
            asm volatile("cp.async.commit_group;" ::: "memory");
            asm volatile("cp.async.wait_group 1;" ::: "memory");
        } else {
            asm volatile("cp.async.wait_group 0;" ::: "memory");
        }
        __syncthreads();
        const uint32_t KB = sb + 9216 + (kt & 1) * 18432;
        const uint32_t VB = KB + 9216;

        // ---- S = Q K^T ----
        float sfr[8][4];
#pragma unroll
        for (int nb = 0; nb < 8; nb++)
#pragma unroll
            for (int q = 0; q < 4; q++) sfr[nb][q] = 0.f;

#pragma unroll
        for (int kk = 0; kk < 4; kk++) {
            uint32_t aq[4], bk4[4][4];
            ldsm4(aq, sb + qa + kk * 32);
#pragma unroll
            for (int t = 0; t < 4; t++)
                ldsm4(bk4[t], KB + (t * 16 + kbr) * 144 + kk * 32 + kbh);
#pragma unroll
            for (int nb = 0; nb < 8; nb++)
                mma16816(sfr[nb], aq, &bk4[nb >> 1][(nb & 1) * 2]);
        }

        // causal mask on the diagonal tile
        if (kt == qt) {
            const int r0 = w * 16 + (lane >> 2), r1 = r0 + 8;
#pragma unroll
            for (int nb = 0; nb < 8; nb++) {
                const int cc = nb * 8 + (lane & 3) * 2;
                if (cc     > r0) sfr[nb][0] = -INFINITY;
                if (cc + 1 > r0) sfr[nb][1] = -INFINITY;
                if (cc     > r1) sfr[nb][2] = -INFINITY;
                if (cc + 1 > r1) sfr[nb][3] = -INFINITY;
            }
        }

        // ---- online softmax ----
        float rm0 = -INFINITY, rm1 = -INFINITY;
#pragma unroll
        for (int nb = 0; nb < 8; nb++) {
            rm0 = fmaxf(rm0, fmaxf(sfr[nb][0], sfr[nb][1]));
            rm1 = fmaxf(rm1, fmaxf(sfr[nb][2], sfr[nb][3]));
        }
        rm0 = fmaxf(rm0, __shfl_xor_sync(0xffffffffu, rm0, 1));
        rm0 = fmaxf(rm0, __shfl_xor_sync(0xffffffffu, rm0, 2));
        rm1 = fmaxf(rm1, __shfl_xor_sync(0xffffffffu, rm1, 1));
        rm1 = fmaxf(rm1, __shfl_xor_sync(0xffffffffu, rm1, 2));
        float nm0 = fmaxf(m0, rm0), nm1 = fmaxf(m1, rm1);
        float c0 = __expf(m0 - nm0), c1 = __expf(m1 - nm1);
        m0 = nm0; m1 = nm1;
        float rs0 = 0.f, rs1 = 0.f;
#pragma unroll
        for (int nb = 0; nb < 8; nb++) {
            sfr[nb][0] = __expf(sfr[nb][0] - m0); rs0 += sfr[nb][0];
            sfr[nb][1] = __expf(sfr[nb][1] - m0); rs0 += sfr[nb][1];
            sfr[nb][2] = __expf(sfr[nb][2] - m1); rs1 += sfr[nb][2];
            sfr[nb][3] = __expf(sfr[nb][3] - m1); rs1 += sfr[nb][3];
        }
        rs0 += __shfl_xor_sync(0xffffffffu, rs0, 1);
        rs0 += __shfl_xor_sync(0xffffffffu, rs0, 2);
        rs1 += __shfl_xor_sync(0xffffffffu, rs1, 1);
        rs1 += __shfl_xor_sync(0xffffffffu, rs1, 2);
        l0 = l0 * c0 + rs0;
        l1 = l1 * c1 + rs1;
#pragma unroll
        for (int nb = 0; nb < 8; nb++) {
            o[nb][0] *= c0; o[nb][1] *= c0; o[nb][2] *= c1; o[nb][3] *= c1;
        }

        // ---- O += P V ----
#pragma unroll
        for (int kk = 0; kk < 4; kk++) {
            uint32_t ap[4];
            ap[0] = pack_h2(sfr[2 * kk][0],     sfr[2 * kk][1]);
            ap[1] = pack_h2(sfr[2 * kk][2],     sfr[2 * kk][3]);
            ap[2] = pack_h2(sfr[2 * kk + 1][0], sfr[2 * kk + 1][1]);
            ap[3] = pack_h2(sfr[2 * kk + 1][2], sfr[2 * kk + 1][3]);
            uint32_t vv[4][4];
#pragma unroll
            for (int t = 0; t < 4; t++)
                ldsm4t(vv[t], VB + (kk * 16 + vkr) * 144 + (t * 16 + vnc) * 2);
#pragma unroll
            for (int nb = 0; nb < 8; nb++)
                mma16816(o[nb], ap, &vv[nb >> 1][(nb & 1) * 2]);
        }
        __syncthreads();
    }

    // ---- epilogue: normalize, store fp16 ----
    const float i0 = 1.f / l0, i1 = 1.f / l1;
    const size_t r0 = tokq + w * 16 + (lane >> 2);
    const size_t r1 = r0 + 8;
#pragma unroll
    for (int nb = 0; nb < 8; nb++) {
        const size_t col = hoff + nb * 8 + (lane & 3) * 2;
        *(uint32_t*)(O + r0 * DMODEL + col) = pack_h2(o[nb][0] * i0, o[nb][1] * i0);
        *(uint32_t*)(O + r1 * DMODEL + col) = pack_h2(o[nb][2] * i1, o[nb][3] * i1);
    }
}

// ---------------------------------------------------------------------------
// Residual add + LayerNorm
// ---------------------------------------------------------------------------
__global__ __launch_bounds__(256) void ln_kernel(
    const float* __restrict__ Osrc, const float* __restrict__ X,
    const float* __restrict__ g, const float* __restrict__ beta,
    float* __restrict__ out)
{
    const int row = blockIdx.x;
    const int tid = threadIdx.x;
    const float* o = Osrc + (size_t)row * DMODEL;
    const float* x = X + (size_t)row * DMODEL;

    float v[4];
    float s = 0.f, s2 = 0.f;
#pragma unroll
    for (int i = 0; i < 4; i++) {
        int c = tid + i * 256;
        float t = o[c] + x[c];
        v[i] = t; s += t; s2 += t * t;
    }
#pragma unroll
    for (int off = 16; off; off >>= 1) {
        s  += __shfl_xor_sync(0xffffffffu, s, off);
        s2 += __shfl_xor_sync(0xffffffffu, s2, off);
    }
    __shared__ float red[18];
    int w = tid >> 5;
    if ((tid & 31) == 0) { red[w] = s; red[8 + w] = s2; }
    __syncthreads();
    if (tid == 0) {
        float S = 0.f, S2 = 0.f;
        for (int k = 0; k < 8; k++) { S += red[k]; S2 += red[8 + k]; }
        red[16] = S; red[17] = S2;
    }
    __syncthreads();
    float mu   = red[16] * (1.f / 1024.f);
    float var  = red[17] * (1.f / 1024.f) - mu * mu;
    float rstd = rsqrtf(var + 1e-5f);
#pragma unroll
    for (int i = 0; i < 4; i++) {
        int c = tid + i * 256;
        out[(size_t)row * DMODEL + c] = (v[i] - mu) * rstd * g[c] + beta[c];
    }
}

// ---------------------------------------------------------------------------
extern "C" void kernel_launch(void* const* d_in, const int* in_sizes, int n_in,
                              void* d_out, int out_size)
{
    const float* X  = (const float*)d_in[0];
    const float* Wq = (const float*)d_in[1];
    const float* bq = (const float*)d_in[2];
    const float* Wk = (const float*)d_in[3];
    const float* bk = (const float*)d_in[4];
    const float* Wv = (const float*)d_in[5];
    const float* bv = (const float*)d_in[6];
    const float* Wo = (const float*)d_in[7];
    const float* bo = (const float*)d_in[8];
    const float* lg = (const float*)d_in[9];
    const float* lb = (const float*)d_in[10];
    float* out = (float*)d_out;

    float* Ob = nullptr;
    cudaGetSymbolAddress((void**)&Ob, g_ob);
    __half *xf, *qf, *kf, *vf, *af, *wf;
    cudaGetSymbolAddress((void**)&xf, g_xf);
    cudaGetSymbolAddress((void**)&qf, g_qf);
    cudaGetSymbolAddress((void**)&kf, g_kf);
    cudaGetSymbolAddress((void**)&vf, g_vf);
    cudaGetSymbolAddress((void**)&af, g_af);
    cudaGetSymbolAddress((void**)&wf, g_wf);

    const int NX4 = (M_TOK * DMODEL) / 4;
    const int NW4 = (DMODEL * DMODEL) / 4;
    const size_t WS = (size_t)DMODEL * DMODEL;

    to_f16<<<NX4 / 256, 256>>>(X, xf, NX4);
    to_f16<<<NW4 / 256, 256>>>(Wq, wf + 0 * WS, NW4);
    to_f16<<<NW4 / 256, 256>>>(Wk, wf + 1 * WS, NW4);
    to_f16<<<NW4 / 256, 256>>>(Wv, wf + 2 * WS, NW4);
    to_f16<<<NW4 / 256, 256>>>(Wo, wf + 3 * WS, NW4);

    const int gemm_smem = 2 * 20480;            // 40,960 B
    cudaFuncSetAttribute(gemm_tc, cudaFuncAttributeMaxDynamicSharedMemorySize, gemm_smem);
    dim3 ggrid(DMODEL / 128, M_TOK / 128);

    const float scale = 0.125f;  // HD^-0.5
    gemm_tc<<<ggrid, 256, gemm_smem>>>(xf, wf + 0 * WS, bq, nullptr, qf, scale);
    gemm_tc<<<ggrid, 256, gemm_smem>>>(xf, wf + 1 * WS, bk, nullptr, kf, 1.f);
    gemm_tc<<<ggrid, 256, gemm_smem>>>(xf, wf + 2 * WS, bv, nullptr, vf, 1.f);

    const int attn_smem = 9216 + 2 * 18432;     // 46,080 B
    cudaFuncSetAttribute(attn_tc, cudaFuncAttributeMaxDynamicSharedMemorySize, attn_smem);
    attn_tc<<<dim3(32, NHEAD, 2), 128, attn_smem>>>(qf, kf, vf, af);

    gemm_tc<<<ggrid, 256, gemm_smem>>>(af, wf + 3 * WS, bo, Ob, nullptr, 1.f);

    ln_kernel<<<M_TOK, 256>>>(Ob, X, lg, lb, out);
}

// round 6
// speedup vs baseline: 6.1038x; 1.0393x over previous
#include <cuda_runtime.h>
#include <cuda_fp16.h>
#include <cstdint>
#include <math.h>

#define M_TOK 4096   // B*S
#define DMODEL 1024
#define NHEAD 16
#define HDIM 64

// fp32 scratch for the LN input
__device__ float g_ob[(size_t)M_TOK * DMODEL];
// fp16 operands
__device__ __half g_xf[(size_t)M_TOK * DMODEL];
__device__ __half g_qf[(size_t)M_TOK * DMODEL], g_kf[(size_t)M_TOK * DMODEL];
__device__ __half g_vf[(size_t)M_TOK * DMODEL], g_af[(size_t)M_TOK * DMODEL];
__device__ __half g_wf[4][(size_t)DMODEL * DMODEL];

// ---------------------------------------------------------------------------
// PTX helpers valid on base sm_103 target
// ---------------------------------------------------------------------------
__device__ __forceinline__ uint32_t smem_to_u32(const void* p) {
    uint32_t a;
    asm("{ .reg .u64 t; cvta.to.shared.u64 t, %1; cvt.u32.u64 %0, t; }" : "=r"(a) : "l"(p));
    return a;
}
__device__ __forceinline__ void cp16(uint32_t dst, const void* src) {
    asm volatile("cp.async.cg.shared.global [%0], [%1], 16;" :: "r"(dst), "l"(src));
}
__device__ __forceinline__ void ldsm4(uint32_t* r, uint32_t addr) {
    asm volatile("ldmatrix.sync.aligned.m8n8.x4.shared.b16 {%0,%1,%2,%3}, [%4];"
                 : "=r"(r[0]), "=r"(r[1]), "=r"(r[2]), "=r"(r[3]) : "r"(addr));
}
__device__ __forceinline__ void ldsm4t(uint32_t* r, uint32_t addr) {
    asm volatile("ldmatrix.sync.aligned.m8n8.x4.trans.shared.b16 {%0,%1,%2,%3}, [%4];"
                 : "=r"(r[0]), "=r"(r[1]), "=r"(r[2]), "=r"(r[3]) : "r"(addr));
}
__device__ __forceinline__ void mma16816(float* c, const uint32_t* a, const uint32_t* b) {
    asm volatile(
        "mma.sync.aligned.m16n8k16.row.col.f32.f16.f16.f32 "
        "{%0,%1,%2,%3}, {%4,%5,%6,%7}, {%8,%9}, {%0,%1,%2,%3};"
        : "+f"(c[0]), "+f"(c[1]), "+f"(c[2]), "+f"(c[3])
        : "r"(a[0]), "r"(a[1]), "r"(a[2]), "r"(a[3]), "r"(b[0]), "r"(b[1]));
}
__device__ __forceinline__ uint32_t pack_h2(float x, float y) {
    __half2 h = __floats2half2_rn(x, y);
    return *reinterpret_cast<uint32_t*>(&h);
}

// ---------------------------------------------------------------------------
// Fused fp32 -> fp16 convert for X (2^20 float4) + 4 weights (2^18 each).
// ---------------------------------------------------------------------------
__global__ __launch_bounds__(256) void conv_all(
    const float* __restrict__ X,
    const float* __restrict__ Wq, const float* __restrict__ Wk,
    const float* __restrict__ Wv, const float* __restrict__ Wo,
    __half* __restrict__ xf, __half* __restrict__ wf)
{
    int i = blockIdx.x * 256 + threadIdx.x;   // 0 .. 2^21-1
    const float* src;
    __half* dst;
    if (i < (1 << 20)) {
        src = X + (size_t)i * 4;
        dst = xf + (size_t)i * 4;
    } else {
        int j = i - (1 << 20);
        int sel = j >> 18;
        int jj = j & ((1 << 18) - 1);
        const float* w4[4] = {Wq, Wk, Wv, Wo};
        src = w4[sel] + (size_t)jj * 4;
        dst = wf + (size_t)sel * DMODEL * DMODEL + (size_t)jj * 4;
    }
    float4 v = *(const float4*)src;
    uint2 o;
    o.x = pack_h2(v.x, v.y);
    o.y = pack_h2(v.z, v.w);
    *(uint2*)dst = o;
}

// ---------------------------------------------------------------------------
// Shared GEMM tile machinery (fp16 HMMA NT, single pass).
// CTA: 128x128 tile, BK=32, 256 threads (8 warps 2x4), warp tile 64x32.
// smem stage (20480 B): A@0, B@10240; rows 80 B (64 B data + 16 pad).
// ---------------------------------------------------------------------------
struct GemmCore {
    uint32_t sbase;
    int tid, lane, wm, wn;
    uint32_t arow, ahalf, brow, bhalf;
    float c[4][4][4];

    __device__ __forceinline__ void init(uint32_t sb, int t) {
        sbase = sb; tid = t; lane = t & 31;
        int wid = t >> 5; wm = wid >> 2; wn = wid & 3;
        arow = lane & 15; ahalf = (uint32_t)(lane >> 4);
        brow = (lane & 7) | (((uint32_t)lane >> 4) << 3);
        bhalf = ((uint32_t)lane >> 3) & 1;
#pragma unroll
        for (int i = 0; i < 4; i++)
#pragma unroll
            for (int j = 0; j < 4; j++)
#pragma unroll
                for (int q = 0; q < 4; q++) c[i][j][q] = 0.f;
    }
    __device__ __forceinline__ void load_stage(const __half* A, const __half* B,
                                               int m0, int n0, int kt, int st) {
        const uint32_t dstb = sbase + st * 20480;
#pragma unroll
        for (int i = 0; i < 4; i++) {
            int cid = i * 256 + tid;
            int t   = cid >> 9;
            int row = (cid >> 2) & 127;
            int kc  = cid & 3;
            const __half* src = t ? B : A;
            const int gbase = t ? n0 : m0;
            cp16(dstb + t * 10240 + row * 80 + kc * 16,
                 src + (size_t)(gbase + row) * DMODEL + kt + kc * 8);
        }
    }
    __device__ __forceinline__ void compute_stage(int st) {
        const uint32_t tb = sbase + st * 20480;
#pragma unroll
        for (int kk = 0; kk < 2; kk++) {
            const uint32_t koff = kk * 32;
            uint32_t ah[4][4], bb[2][4];
#pragma unroll
            for (int i = 0; i < 4; i++)
                ldsm4(ah[i], tb + (wm * 64 + i * 16 + arow) * 80 + koff + ahalf * 16);
#pragma unroll
            for (int j = 0; j < 2; j++)
                ldsm4(bb[j], tb + 10240 + (wn * 32 + j * 16 + brow) * 80 + koff + bhalf * 16);
#pragma unroll
            for (int i = 0; i < 4; i++)
#pragma unroll
                for (int j = 0; j < 4; j++)
                    mma16816(c[i][j], ah[i], &bb[j >> 1][(j & 1) * 2]);
        }
    }
    __device__ __forceinline__ void run(const __half* A, const __half* B, int m0, int n0) {
        load_stage(A, B, m0, n0, 0, 0);
        asm volatile("cp.async.commit_group;" ::: "memory");
        const int NK = DMODEL / 32;
        for (int ch = 0; ch < NK; ch++) {
            if (ch + 1 < NK) {
                load_stage(A, B, m0, n0, (ch + 1) * 32, (ch + 1) & 1);
                asm volatile("cp.async.commit_group;" ::: "memory");
                asm volatile("cp.async.wait_group 1;" ::: "memory");
            } else {
                asm volatile("cp.async.wait_group 0;" ::: "memory");
            }
            __syncthreads();
            compute_stage(ch & 1);
            __syncthreads();
        }
    }
};

// Fused QKV projection: grid.x = 24 (seg = bx/8), grid.y = 32.
__global__ __launch_bounds__(256) void gemm_qkv(
    const __half* __restrict__ Xf, const __half* __restrict__ Wf,
    const float* __restrict__ bq, const float* __restrict__ bk,
    const float* __restrict__ bv,
    __half* __restrict__ Qf, __half* __restrict__ Kf, __half* __restrict__ Vf)
{
    extern __shared__ __align__(128) char smem[];
    const int seg = blockIdx.x >> 3;
    const int n0  = (blockIdx.x & 7) * 128;
    const int m0  = blockIdx.y * 128;
    const __half* B = Wf + (size_t)seg * DMODEL * DMODEL;
    const float* bias = (seg == 0) ? bq : (seg == 1) ? bk : bv;
    __half* Ch = (seg == 0) ? Qf : (seg == 1) ? Kf : Vf;
    const float alpha = (seg == 0) ? 0.125f : 1.f;

    GemmCore g;
    g.init(smem_to_u32(smem), threadIdx.x);
    g.run(Xf, B, m0, n0);

    const int lane = g.lane;
#pragma unroll
    for (int i = 0; i < 4; i++) {
        const int r = m0 + g.wm * 64 + i * 16 + (lane >> 2);
#pragma unroll
        for (int j = 0; j < 4; j++) {
            const int col = n0 + g.wn * 32 + j * 8 + (lane & 3) * 2;
            const float b0 = bias[col], b1 = bias[col + 1];
            *(uint32_t*)(Ch + (size_t)r * DMODEL + col) =
                pack_h2(alpha * (g.c[i][j][0] + b0), alpha * (g.c[i][j][1] + b1));
            *(uint32_t*)(Ch + (size_t)(r + 8) * DMODEL + col) =
                pack_h2(alpha * (g.c[i][j][2] + b0), alpha * (g.c[i][j][3] + b1));
        }
    }
}

// Output projection: fp32 output.
__global__ __launch_bounds__(256) void gemm_out(
    const __half* __restrict__ A, const __half* __restrict__ B,
    const float* __restrict__ bias, float* __restrict__ Cf)
{
    extern __shared__ __align__(128) char smem[];
    const int n0 = blockIdx.x * 128;
    const int m0 = blockIdx.y * 128;

    GemmCore g;
    g.init(smem_to_u32(smem), threadIdx.x);
    g.run(A, B, m0, n0);

    const int lane = g.lane;
#pragma unroll
    for (int i = 0; i < 4; i++) {
        const int r = m0 + g.wm * 64 + i * 16 + (lane >> 2);
#pragma unroll
        for (int j = 0; j < 4; j++) {
            const int col = n0 + g.wn * 32 + j * 8 + (lane & 3) * 2;
            const float b0 = bias[col], b1 = bias[col + 1];
            float2 w0, w1;
            w0.x = g.c[i][j][0] + b0; w0.y = g.c[i][j][1] + b1;
            w1.x = g.c[i][j][2] + b0; w1.y = g.c[i][j][3] + b1;
            *(float2*)(Cf + (size_t)r * DMODEL + col)       = w0;
            *(float2*)(Cf + (size_t)(r + 8) * DMODEL + col) = w1;
        }
    }
}

// ---------------------------------------------------------------------------
// fp16 HMMA flash attention, causal. CTA = (128-q tile, head, batch), 256 thr.
// 8 warps x 16 query rows. K/V tiles 64 rows, double buffered.
// smem (55296 B): Q@0 (128x144 = 18432); stage s at 18432 + s*18432:
// K@+0 (64x144=9216), V@+9216.
// ---------------------------------------------------------------------------
__global__ __launch_bounds__(256) void attn_tc(
    const __half* __restrict__ Q, const __half* __restrict__ K,
    const __half* __restrict__ V, __half* __restrict__ O)
{
    extern __shared__ __align__(128) char smem[];
    const uint32_t sb = smem_to_u32(smem);
    const int tid = threadIdx.x, lane = tid & 31, w = tid >> 5;
    const int qt = 15 - blockIdx.x;      // heavy tiles first
    const int h  = blockIdx.y;
    const int b  = blockIdx.z;
    const size_t tokq = (size_t)b * 2048 + qt * 128;
    const size_t hoff = (size_t)h * HDIM;

    // Q tile: 128 rows x 8 chunks of 16B = 1024 cp16, 4 per thread
#pragma unroll
    for (int i = 0; i < 4; i++) {
        int c = tid + i * 256;
        int r = c >> 3, kc = c & 7;
        cp16(sb + r * 144 + kc * 16, Q + (tokq + r) * DMODEL + hoff + kc * 8);
    }
    auto load_kv = [&](int kt, int s) {
        const size_t tokk = (size_t)b * 2048 + kt * 64;
        const uint32_t db = sb + 18432 + s * 18432;
#pragma unroll
        for (int i = 0; i < 4; i++) {
            int c = tid + i * 256;
            int t = c >> 9, r = (c >> 3) & 63, kc = c & 7;
            const __half* src = t ? V : K;
            cp16(db + t * 9216 + r * 144 + kc * 16, src + (tokk + r) * DMODEL + hoff + kc * 8);
        }
    };
    load_kv(0, 0);
    asm volatile("cp.async.commit_group;" ::: "memory");

    float o[8][4];
#pragma unroll
    for (int nb = 0; nb < 8; nb++)
#pragma unroll
        for (int q = 0; q < 4; q++) o[nb][q] = 0.f;
    float m0 = -INFINITY, m1 = -INFINITY, l0 = 0.f, l1 = 0.f;

    const uint32_t qa  = (uint32_t)((w * 16 + (lane & 15)) * 144 + (lane >> 4) * 16);
    const uint32_t kbr = (uint32_t)((lane & 7) | ((lane >> 4) << 3));
    const uint32_t kbh = (uint32_t)(((lane >> 3) & 1) * 16);
    const uint32_t vkr = (uint32_t)((lane & 7) + ((lane >> 3) & 1) * 8);
    const uint32_t vnc = (uint32_t)(((lane >> 4) & 1) * 8);

    // per-lane global row ids (for causal mask)
    const int gr0 = qt * 128 + w * 16 + (lane >> 2);
    const int gr1 = gr0 + 8;

    const int kmax = 2 * qt + 1;
    for (int kt = 0; kt <= kmax; kt++) {
        if (kt < kmax) {
            load_kv(kt + 1, (kt + 1) & 1);
            asm volatile("cp.async.commit_group;" ::: "memory");
            asm volatile("cp.async.wait_group 1;" ::: "memory");
        } else {
            asm volatile("cp.async.wait_group 0;" ::: "memory");
        }
        __syncthreads();
        const uint32_t KB = sb + 18432 + (kt & 1) * 18432;
        const uint32_t VB = KB + 9216;

        // ---- S = Q K^T ----
        float sfr[8][4];
#pragma unroll
        for (int nb = 0; nb < 8; nb++)
#pragma unroll
            for (int q = 0; q < 4; q++) sfr[nb][q] = 0.f;

#pragma unroll
        for (int kk = 0; kk < 4; kk++) {
            uint32_t aq[4], bk4[4][4];
            ldsm4(aq, sb + qa + kk * 32);
#pragma unroll
            for (int t = 0; t < 4; t++)
                ldsm4(bk4[t], KB + (t * 16 + kbr) * 144 + kk * 32 + kbh);
#pragma unroll
            for (int nb = 0; nb < 8; nb++)
                mma16816(sfr[nb], aq, &bk4[nb >> 1][(nb & 1) * 2]);
        }

        // causal mask (only the last two K tiles can intersect the diagonal)
        if (kt >= kmax - 1) {
            const int cb = kt * 64;
#pragma unroll
            for (int nb = 0; nb < 8; nb++) {
                const int cc = cb + nb * 8 + (lane & 3) * 2;
                if (cc     > gr0) sfr[nb][0] = -INFINITY;
                if (cc + 1 > gr0) sfr[nb][1] = -INFINITY;
                if (cc     > gr1) sfr[nb][2] = -INFINITY;
                if (cc + 1 > gr1) sfr[nb][3] = -INFINITY;
            }
        }

        // ---- online softmax ----
        float rm0 = -INFINITY, rm1 = -INFINITY;
#pragma unroll
        for (int nb = 0; nb < 8; nb++) {
            rm0 = fmaxf(rm0, fmaxf(sfr[nb][0], sfr[nb][1]));
            rm1 = fmaxf(rm1, fmaxf(sfr[nb][2], sfr[nb][3]));
        }
        rm0 = fmaxf(rm0, __shfl_xor_sync(0xffffffffu, rm0, 1));
        rm0 = fmaxf(rm0, __shfl_xor_sync(0xffffffffu, rm0, 2));
        rm1 = fmaxf(rm1, __shfl_xor_sync(0xffffffffu, rm1, 1));
        rm1 = fmaxf(rm1, __shfl_xor_sync(0xffffffffu, rm1, 2));
        float nm0 = fmaxf(m0, rm0), nm1 = fmaxf(m1, rm1);
        float c0 = __expf(m0 - nm0), c1 = __expf(m1 - nm1);
        m0 = nm0; m1 = nm1;
        float rs0 = 0.f, rs1 = 0.f;
#pragma unroll
        for (int nb = 0; nb < 8; nb++) {
            sfr[nb][0] = __expf(sfr[nb][0] - m0); rs0 += sfr[nb][0];
            sfr[nb][1] = __expf(sfr[nb][1] - m0); rs0 += sfr[nb][1];
            sfr[nb][2] = __expf(sfr[nb][2] - m1); rs1 += sfr[nb][2];
            sfr[nb][3] = __expf(sfr[nb][3] - m1); rs1 += sfr[nb][3];
        }
        rs0 += __shfl_xor_sync(0xffffffffu, rs0, 1);
        rs0 += __shfl_xor_sync(0xffffffffu, rs0, 2);
        rs1 += __shfl_xor_sync(0xffffffffu, rs1, 1);
        rs1 += __shfl_xor_sync(0xffffffffu, rs1, 2);
        l0 = l0 * c0 + rs0;
        l1 = l1 * c1 + rs1;
#pragma unroll
        for (int nb = 0; nb < 8; nb++) {
            o[nb][0] *= c0; o[nb][1] *= c0; o[nb][2] *= c1; o[nb][3] *= c1;
        }

        // ---- O += P V ----
#pragma unroll
        for (int kk = 0; kk < 4; kk++) {
            uint32_t ap[4];
            ap[0] = pack_h2(sfr[2 * kk][0],     sfr[2 * kk][1]);
            ap[1] = pack_h2(sfr[2 * kk][2],     sfr[2 * kk][3]);
            ap[2] = pack_h2(sfr[2 * kk + 1][0], sfr[2 * kk + 1][1]);
            ap[3] = pack_h2(sfr[2 * kk + 1][2], sfr[2 * kk + 1][3]);
            uint32_t vv[4][4];
#pragma unroll
            for (int t = 0; t < 4; t++)
                ldsm4t(vv[t], VB + (kk * 16 + vkr) * 144 + (t * 16 + vnc) * 2);
#pragma unroll
            for (int nb = 0; nb < 8; nb++)
                mma16816(o[nb], ap, &vv[nb >> 1][(nb & 1) * 2]);
        }
        __syncthreads();
    }

    // ---- epilogue: normalize, store fp16 ----
    const float i0 = 1.f / l0, i1 = 1.f / l1;
    const size_t r0 = tokq + w * 16 + (lane >> 2);
    const size_t r1 = r0 + 8;
#pragma unroll
    for (int nb = 0; nb < 8; nb++) {
        const size_t col = hoff + nb * 8 + (lane & 3) * 2;
        *(uint32_t*)(O + r0 * DMODEL + col) = pack_h2(o[nb][0] * i0, o[nb][1] * i0);
        *(uint32_t*)(O + r1 * DMODEL + col) = pack_h2(o[nb][2] * i1, o[nb][3] * i1);
    }
}

// ---------------------------------------------------------------------------
// Residual add + LayerNorm
// ---------------------------------------------------------------------------
__global__ __launch_bounds__(256) void ln_kernel(
    const float* __restrict__ Osrc, const float* __restrict__ X,
    const float* __restrict__ g, const float* __restrict__ beta,
    float* __restrict__ out)
{
    const int row = blockIdx.x;
    const int tid = threadIdx.x;
    const float* o = Osrc + (size_t)row * DMODEL;
    const float* x = X + (size_t)row * DMODEL;

    float v[4];
    float s = 0.f, s2 = 0.f;
#pragma unroll
    for (int i = 0; i < 4; i++) {
        int c = tid + i * 256;
        float t = o[c] + x[c];
        v[i] = t; s += t; s2 += t * t;
    }
#pragma unroll
    for (int off = 16; off; off >>= 1) {
        s  += __shfl_xor_sync(0xffffffffu, s, off);
        s2 += __shfl_xor_sync(0xffffffffu, s2, off);
    }
    __shared__ float red[18];
    int w = tid >> 5;
    if ((tid & 31) == 0) { red[w] = s; red[8 + w] = s2; }
    __syncthreads();
    if (tid == 0) {
        float S = 0.f, S2 = 0.f;
        for (int k = 0; k < 8; k++) { S += red[k]; S2 += red[8 + k]; }
        red[16] = S; red[17] = S2;
    }
    __syncthreads();
    float mu   = red[16] * (1.f / 1024.f);
    float var  = red[17] * (1.f / 1024.f) - mu * mu;
    float rstd = rsqrtf(var + 1e-5f);
#pragma unroll
    for (int i = 0; i < 4; i++) {
        int c = tid + i * 256;
        out[(size_t)row * DMODEL + c] = (v[i] - mu) * rstd * g[c] + beta[c];
    }
}

// ---------------------------------------------------------------------------
extern "C" void kernel_launch(void* const* d_in, const int* in_sizes, int n_in,
                              void* d_out, int out_size)
{
    const float* X  = (const float*)d_in[0];
    const float* Wq = (const float*)d_in[1];
    const float* bq = (const float*)d_in[2];
    const float* Wk = (const float*)d_in[3];
    const float* bk = (const float*)d_in[4];
    const float* Wv = (const float*)d_in[5];
    const float* bv = (const float*)d_in[6];
    const float* Wo = (const float*)d_in[7];
    const float* bo = (const float*)d_in[8];
    const float* lg = (const float*)d_in[9];
    const float* lb = (const float*)d_in[10];
    float* out = (float*)d_out;

    float* Ob = nullptr;
    cudaGetSymbolAddress((void**)&Ob, g_ob);
    __half *xf, *qf, *kf, *vf, *af, *wf;
    cudaGetSymbolAddress((void**)&xf, g_xf);
    cudaGetSymbolAddress((void**)&qf, g_qf);
    cudaGetSymbolAddress((void**)&kf, g_kf);
    cudaGetSymbolAddress((void**)&vf, g_vf);
    cudaGetSymbolAddress((void**)&af, g_af);
    cudaGetSymbolAddress((void**)&wf, g_wf);

    const size_t WS = (size_t)DMODEL * DMODEL;

    // 2^21 float4 groups: X (2^20) + 4 weights (2^18 each)
    conv_all<<<(1 << 21) / 256, 256>>>(X, Wq, Wk, Wv, Wo, xf, wf);

    const int gemm_smem = 2 * 20480;            // 40,960 B
    cudaFuncSetAttribute(gemm_qkv, cudaFuncAttributeMaxDynamicSharedMemorySize, gemm_smem);
    cudaFuncSetAttribute(gemm_out, cudaFuncAttributeMaxDynamicSharedMemorySize, gemm_smem);

    gemm_qkv<<<dim3(24, 32), 256, gemm_smem>>>(xf, wf, bq, bk, bv, qf, kf, vf);

    const int attn_smem = 18432 + 2 * 18432;    // 55,296 B
    cudaFuncSetAttribute(attn_tc, cudaFuncAttributeMaxDynamicSharedMemorySize, attn_smem);
    attn_tc<<<dim3(16, NHEAD, 2), 256, attn_smem>>>(qf, kf, vf, af);

    gemm_out<<<dim3(8, 32), 256, gemm_smem>>>(af, wf + 3 * WS, bo, Ob);

    ln_kernel<<<M_TOK, 256>>>(Ob, X, lg, lb, out);
}

// round 7
// speedup vs baseline: 6.1651x; 1.0101x over previous
#include <cuda_runtime.h>
#include <cuda_fp16.h>
#include <cstdint>
#include <math.h>

#define M_TOK 4096   // B*S
#define DMODEL 1024
#define NHEAD 16
#define HDIM 64

// fp32 scratch for the LN input
__device__ float g_ob[(size_t)M_TOK * DMODEL];
// fp16 operands
__device__ __half g_xf[(size_t)M_TOK * DMODEL];
__device__ __half g_qf[(size_t)M_TOK * DMODEL], g_kf[(size_t)M_TOK * DMODEL];
__device__ __half g_vf[(size_t)M_TOK * DMODEL], g_af[(size_t)M_TOK * DMODEL];
__device__ __half g_wf[4][(size_t)DMODEL * DMODEL];

// ---------------------------------------------------------------------------
// PTX helpers valid on base sm_103 target
// ---------------------------------------------------------------------------
__device__ __forceinline__ uint32_t smem_to_u32(const void* p) {
    uint32_t a;
    asm("{ .reg .u64 t; cvta.to.shared.u64 t, %1; cvt.u32.u64 %0, t; }" : "=r"(a) : "l"(p));
    return a;
}
__device__ __forceinline__ void cp16(uint32_t dst, const void* src) {
    asm volatile("cp.async.cg.shared.global [%0], [%1], 16;" :: "r"(dst), "l"(src));
}
__device__ __forceinline__ void cp_commit() {
    asm volatile("cp.async.commit_group;" ::: "memory");
}
template <int N>
__device__ __forceinline__ void cp_wait() {
    asm volatile("cp.async.wait_group %0;" :: "n"(N) : "memory");
}
__device__ __forceinline__ void ldsm4(uint32_t* r, uint32_t addr) {
    asm volatile("ldmatrix.sync.aligned.m8n8.x4.shared.b16 {%0,%1,%2,%3}, [%4];"
                 : "=r"(r[0]), "=r"(r[1]), "=r"(r[2]), "=r"(r[3]) : "r"(addr));
}
__device__ __forceinline__ void ldsm4t(uint32_t* r, uint32_t addr) {
    asm volatile("ldmatrix.sync.aligned.m8n8.x4.trans.shared.b16 {%0,%1,%2,%3}, [%4];"
                 : "=r"(r[0]), "=r"(r[1]), "=r"(r[2]), "=r"(r[3]) : "r"(addr));
}
__device__ __forceinline__ void mma16816(float* c, const uint32_t* a, const uint32_t* b) {
    asm volatile(
        "mma.sync.aligned.m16n8k16.row.col.f32.f16.f16.f32 "
        "{%0,%1,%2,%3}, {%4,%5,%6,%7}, {%8,%9}, {%0,%1,%2,%3};"
        : "+f"(c[0]), "+f"(c[1]), "+f"(c[2]), "+f"(c[3])
        : "r"(a[0]), "r"(a[1]), "r"(a[2]), "r"(a[3]), "r"(b[0]), "r"(b[1]));
}
__device__ __forceinline__ uint32_t pack_h2(float x, float y) {
    __half2 h = __floats2half2_rn(x, y);
    return *reinterpret_cast<uint32_t*>(&h);
}

// ---------------------------------------------------------------------------
// Fused fp32 -> fp16 convert for X (2^20 float4) + 4 weights (2^18 each).
// ---------------------------------------------------------------------------
__global__ __launch_bounds__(256) void conv_all(
    const float* __restrict__ X,
    const float* __restrict__ Wq, const float* __restrict__ Wk,
    const float* __restrict__ Wv, const float* __restrict__ Wo,
    __half* __restrict__ xf, __half* __restrict__ wf)
{
    int i = blockIdx.x * 256 + threadIdx.x;   // 0 .. 2^21-1
    const float* src;
    __half* dst;
    if (i < (1 << 20)) {
        src = X + (size_t)i * 4;
        dst = xf + (size_t)i * 4;
    } else {
        int j = i - (1 << 20);
        int sel = j >> 18;
        int jj = j & ((1 << 18) - 1);
        const float* w4[4] = {Wq, Wk, Wv, Wo};
        src = w4[sel] + (size_t)jj * 4;
        dst = wf + (size_t)sel * DMODEL * DMODEL + (size_t)jj * 4;
    }
    float4 v = *(const float4*)src;
    uint2 o;
    o.x = pack_h2(v.x, v.y);
    o.y = pack_h2(v.z, v.w);
    *(uint2*)dst = o;
}

// ---------------------------------------------------------------------------
// Shared GEMM tile machinery (fp16 HMMA NT, single pass).
// CTA: 128x128 tile, BK=32, 256 threads (8 warps 2x4), warp tile 64x32.
// 3-stage cp.async ring (stage 20480 B: A@0, B@10240; rows 80 B),
// ONE __syncthreads per K-chunk.
// ---------------------------------------------------------------------------
struct GemmCore {
    uint32_t sbase;
    int tid, lane, wm, wn;
    uint32_t arow, ahalf, brow, bhalf;
    float c[4][4][4];

    __device__ __forceinline__ void init(uint32_t sb, int t) {
        sbase = sb; tid = t; lane = t & 31;
        int wid = t >> 5; wm = wid >> 2; wn = wid & 3;
        arow = lane & 15; ahalf = (uint32_t)(lane >> 4);
        brow = (lane & 7) | (((uint32_t)lane >> 4) << 3);
        bhalf = ((uint32_t)lane >> 3) & 1;
#pragma unroll
        for (int i = 0; i < 4; i++)
#pragma unroll
            for (int j = 0; j < 4; j++)
#pragma unroll
                for (int q = 0; q < 4; q++) c[i][j][q] = 0.f;
    }
    __device__ __forceinline__ void load_stage(const __half* A, const __half* B,
                                               int m0, int n0, int kt, int st) {
        const uint32_t dstb = sbase + st * 20480;
#pragma unroll
        for (int i = 0; i < 4; i++) {
            int cid = i * 256 + tid;
            int t   = cid >> 9;
            int row = (cid >> 2) & 127;
            int kc  = cid & 3;
            const __half* src = t ? B : A;
            const int gbase = t ? n0 : m0;
            cp16(dstb + t * 10240 + row * 80 + kc * 16,
                 src + (size_t)(gbase + row) * DMODEL + kt + kc * 8);
        }
    }
    __device__ __forceinline__ void compute_stage(int st) {
        const uint32_t tb = sbase + st * 20480;
#pragma unroll
        for (int kk = 0; kk < 2; kk++) {
            const uint32_t koff = kk * 32;
            uint32_t ah[4][4], bb[2][4];
#pragma unroll
            for (int i = 0; i < 4; i++)
                ldsm4(ah[i], tb + (wm * 64 + i * 16 + arow) * 80 + koff + ahalf * 16);
#pragma unroll
            for (int j = 0; j < 2; j++)
                ldsm4(bb[j], tb + 10240 + (wn * 32 + j * 16 + brow) * 80 + koff + bhalf * 16);
#pragma unroll
            for (int i = 0; i < 4; i++)
#pragma unroll
                for (int j = 0; j < 4; j++)
                    mma16816(c[i][j], ah[i], &bb[j >> 1][(j & 1) * 2]);
        }
    }
    __device__ __forceinline__ void run(const __half* A, const __half* B, int m0, int n0) {
        const int NK = DMODEL / 32;   // 32
        load_stage(A, B, m0, n0, 0, 0); cp_commit();
        load_stage(A, B, m0, n0, 32, 1); cp_commit();
        // stage ring: compute ch%3; in flight ch+1; load target (ch+2)%3
        for (int ch = 0; ch < NK; ch++) {
            if (ch + 1 < NK) cp_wait<1>(); else cp_wait<0>();
            __syncthreads();              // stage (ch-1)%3 now free for reuse
            if (ch + 2 < NK) {
                load_stage(A, B, m0, n0, (ch + 2) * 32, (ch + 2) % 3);
                cp_commit();
            }
            compute_stage(ch % 3);
        }
    }
};

// Fused QKV projection: grid.x = 24 (seg = bx/8), grid.y = 32.
__global__ __launch_bounds__(256) void gemm_qkv(
    const __half* __restrict__ Xf, const __half* __restrict__ Wf,
    const float* __restrict__ bq, const float* __restrict__ bk,
    const float* __restrict__ bv,
    __half* __restrict__ Qf, __half* __restrict__ Kf, __half* __restrict__ Vf)
{
    extern __shared__ __align__(128) char smem[];
    const int seg = blockIdx.x >> 3;
    const int n0  = (blockIdx.x & 7) * 128;
    const int m0  = blockIdx.y * 128;
    const __half* B = Wf + (size_t)seg * DMODEL * DMODEL;
    const float* bias = (seg == 0) ? bq : (seg == 1) ? bk : bv;
    __half* Ch = (seg == 0) ? Qf : (seg == 1) ? Kf : Vf;
    const float alpha = (seg == 0) ? 0.125f : 1.f;

    GemmCore g;
    g.init(smem_to_u32(smem), threadIdx.x);
    g.run(Xf, B, m0, n0);

    const int lane = g.lane;
#pragma unroll
    for (int i = 0; i < 4; i++) {
        const int r = m0 + g.wm * 64 + i * 16 + (lane >> 2);
#pragma unroll
        for (int j = 0; j < 4; j++) {
            const int col = n0 + g.wn * 32 + j * 8 + (lane & 3) * 2;
            const float b0 = bias[col], b1 = bias[col + 1];
            *(uint32_t*)(Ch + (size_t)r * DMODEL + col) =
                pack_h2(alpha * (g.c[i][j][0] + b0), alpha * (g.c[i][j][1] + b1));
            *(uint32_t*)(Ch + (size_t)(r + 8) * DMODEL + col) =
                pack_h2(alpha * (g.c[i][j][2] + b0), alpha * (g.c[i][j][3] + b1));
        }
    }
}

// Output projection: fp32 output.
__global__ __launch_bounds__(256) void gemm_out(
    const __half* __restrict__ A, const __half* __restrict__ B,
    const float* __restrict__ bias, float* __restrict__ Cf)
{
    extern __shared__ __align__(128) char smem[];
    const int n0 = blockIdx.x * 128;
    const int m0 = blockIdx.y * 128;

    GemmCore g;
    g.init(smem_to_u32(smem), threadIdx.x);
    g.run(A, B, m0, n0);

    const int lane = g.lane;
#pragma unroll
    for (int i = 0; i < 4; i++) {
        const int r = m0 + g.wm * 64 + i * 16 + (lane >> 2);
#pragma unroll
        for (int j = 0; j < 4; j++) {
            const int col = n0 + g.wn * 32 + j * 8 + (lane & 3) * 2;
            const float b0 = bias[col], b1 = bias[col + 1];
            float2 w0, w1;
            w0.x = g.c[i][j][0] + b0; w0.y = g.c[i][j][1] + b1;
            w1.x = g.c[i][j][2] + b0; w1.y = g.c[i][j][3] + b1;
            *(float2*)(Cf + (size_t)r * DMODEL + col)       = w0;
            *(float2*)(Cf + (size_t)(r + 8) * DMODEL + col) = w1;
        }
    }
}

// ---------------------------------------------------------------------------
// fp16 HMMA flash attention, causal. CTA = (128-q tile, head, batch), 256 thr.
// 8 warps x 16 query rows. K/V tiles 64 rows, 3-stage cp.async ring,
// ONE __syncthreads per K-tile.
// smem (73728 B): Q@0 (128x144 = 18432); stage s at 18432 + s*18432:
// K@+0 (64x144=9216), V@+9216.
// ---------------------------------------------------------------------------
__global__ __launch_bounds__(256) void attn_tc(
    const __half* __restrict__ Q, const __half* __restrict__ K,
    const __half* __restrict__ V, __half* __restrict__ O)
{
    extern __shared__ __align__(128) char smem[];
    const uint32_t sb = smem_to_u32(smem);
    const int tid = threadIdx.x, lane = tid & 31, w = tid >> 5;
    const int qt = 15 - blockIdx.x;      // heavy tiles first
    const int h  = blockIdx.y;
    const int b  = blockIdx.z;
    const size_t tokq = (size_t)b * 2048 + qt * 128;
    const size_t hoff = (size_t)h * HDIM;

    auto load_kv = [&](int kt, int s) {
        const size_t tokk = (size_t)b * 2048 + kt * 64;
        const uint32_t db = sb + 18432 + s * 18432;
#pragma unroll
        for (int i = 0; i < 4; i++) {
            int c = tid + i * 256;
            int t = c >> 9, r = (c >> 3) & 63, kc = c & 7;
            const __half* src = t ? V : K;
            cp16(db + t * 9216 + r * 144 + kc * 16, src + (tokk + r) * DMODEL + hoff + kc * 8);
        }
    };

    // Q tile (group 0 together with KV stage 0)
#pragma unroll
    for (int i = 0; i < 4; i++) {
        int c = tid + i * 256;
        int r = c >> 3, kc = c & 7;
        cp16(sb + r * 144 + kc * 16, Q + (tokq + r) * DMODEL + hoff + kc * 8);
    }
    const int kmax = 2 * qt + 1;        // >= 1 always
    load_kv(0, 0); cp_commit();
    load_kv(1, 1); cp_commit();

    float o[8][4];
#pragma unroll
    for (int nb = 0; nb < 8; nb++)
#pragma unroll
        for (int q = 0; q < 4; q++) o[nb][q] = 0.f;
    float m0 = -INFINITY, m1 = -INFINITY, l0 = 0.f, l1 = 0.f;

    const uint32_t qa  = (uint32_t)((w * 16 + (lane & 15)) * 144 + (lane >> 4) * 16);
    const uint32_t kbr = (uint32_t)((lane & 7) | ((lane >> 4) << 3));
    const uint32_t kbh = (uint32_t)(((lane >> 3) & 1) * 16);
    const uint32_t vkr = (uint32_t)((lane & 7) + ((lane >> 3) & 1) * 8);
    const uint32_t vnc = (uint32_t)(((lane >> 4) & 1) * 8);

    const int gr0 = qt * 128 + w * 16 + (lane >> 2);
    const int gr1 = gr0 + 8;

    for (int kt = 0; kt <= kmax; kt++) {
        if (kt + 1 <= kmax) cp_wait<1>(); else cp_wait<0>();
        __syncthreads();                  // stage (kt-1)%3 now free
        if (kt + 2 <= kmax) { load_kv(kt + 2, (kt + 2) % 3); cp_commit(); }

        const uint32_t KB = sb + 18432 + (kt % 3) * 18432;
        const uint32_t VB = KB + 9216;

        // ---- S = Q K^T ----
        float sfr[8][4];
#pragma unroll
        for (int nb = 0; nb < 8; nb++)
#pragma unroll
            for (int q = 0; q < 4; q++) sfr[nb][q] = 0.f;

#pragma unroll
        for (int kk = 0; kk < 4; kk++) {
            uint32_t aq[4], bk4[4][4];
            ldsm4(aq, sb + qa + kk * 32);
#pragma unroll
            for (int t = 0; t < 4; t++)
                ldsm4(bk4[t], KB + (t * 16 + kbr) * 144 + kk * 32 + kbh);
#pragma unroll
            for (int nb = 0; nb < 8; nb++)
                mma16816(sfr[nb], aq, &bk4[nb >> 1][(nb & 1) * 2]);
        }

        // causal mask (only the last two K tiles can intersect the diagonal)
        if (kt >= kmax - 1) {
            const int cb = kt * 64;
#pragma unroll
            for (int nb = 0; nb < 8; nb++) {
                const int cc = cb + nb * 8 + (lane & 3) * 2;
                if (cc     > gr0) sfr[nb][0] = -INFINITY;
                if (cc + 1 > gr0) sfr[nb][1] = -INFINITY;
                if (cc     > gr1) sfr[nb][2] = -INFINITY;
                if (cc + 1 > gr1) sfr[nb][3] = -INFINITY;
            }
        }

        // ---- online softmax ----
        float rm0 = -INFINITY, rm1 = -INFINITY;
#pragma unroll
        for (int nb = 0; nb < 8; nb++) {
            rm0 = fmaxf(rm0, fmaxf(sfr[nb][0], sfr[nb][1]));
            rm1 = fmaxf(rm1, fmaxf(sfr[nb][2], sfr[nb][3]));
        }
        rm0 = fmaxf(rm0, __shfl_xor_sync(0xffffffffu, rm0, 1));
        rm0 = fmaxf(rm0, __shfl_xor_sync(0xffffffffu, rm0, 2));
        rm1 = fmaxf(rm1, __shfl_xor_sync(0xffffffffu, rm1, 1));
        rm1 = fmaxf(rm1, __shfl_xor_sync(0xffffffffu, rm1, 2));
        float nm0 = fmaxf(m0, rm0), nm1 = fmaxf(m1, rm1);
        float c0 = __expf(m0 - nm0), c1 = __expf(m1 - nm1);
        m0 = nm0; m1 = nm1;
        float rs0 = 0.f, rs1 = 0.f;
#pragma unroll
        for (int nb = 0; nb < 8; nb++) {
            sfr[nb][0] = __expf(sfr[nb][0] - m0); rs0 += sfr[nb][0];
            sfr[nb][1] = __expf(sfr[nb][1] - m0); rs0 += sfr[nb][1];
            sfr[nb][2] = __expf(sfr[nb][2] - m1); rs1 += sfr[nb][2];
            sfr[nb][3] = __expf(sfr[nb][3] - m1); rs1 += sfr[nb][3];
        }
        rs0 += __shfl_xor_sync(0xffffffffu, rs0, 1);
        rs0 += __shfl_xor_sync(0xffffffffu, rs0, 2);
        rs1 += __shfl_xor_sync(0xffffffffu, rs1, 1);
        rs1 += __shfl_xor_sync(0xffffffffu, rs1, 2);
        l0 = l0 * c0 + rs0;
        l1 = l1 * c1 + rs1;
#pragma unroll
        for (int nb = 0; nb < 8; nb++) {
            o[nb][0] *= c0; o[nb][1] *= c0; o[nb][2] *= c1; o[nb][3] *= c1;
        }

        // ---- O += P V ----
#pragma unroll
        for (int kk = 0; kk < 4; kk++) {
            uint32_t ap[4];
            ap[0] = pack_h2(sfr[2 * kk][0],     sfr[2 * kk][1]);
            ap[1] = pack_h2(sfr[2 * kk][2],     sfr[2 * kk][3]);
            ap[2] = pack_h2(sfr[2 * kk + 1][0], sfr[2 * kk + 1][1]);
            ap[3] = pack_h2(sfr[2 * kk + 1][2], sfr[2 * kk + 1][3]);
            uint32_t vv[4][4];
#pragma unroll
            for (int t = 0; t < 4; t++)
                ldsm4t(vv[t], VB + (kk * 16 + vkr) * 144 + (t * 16 + vnc) * 2);
#pragma unroll
            for (int nb = 0; nb < 8; nb++)
                mma16816(o[nb], ap, &vv[nb >> 1][(nb & 1) * 2]);
        }
    }

    // ---- epilogue: normalize, store fp16 ----
    const float i0 = 1.f / l0, i1 = 1.f / l1;
    const size_t r0 = tokq + w * 16 + (lane >> 2);
    const size_t r1 = r0 + 8;
#pragma unroll
    for (int nb = 0; nb < 8; nb++) {
        const size_t col = hoff + nb * 8 + (lane & 3) * 2;
        *(uint32_t*)(O + r0 * DMODEL + col) = pack_h2(o[nb][0] * i0, o[nb][1] * i0);
        *(uint32_t*)(O + r1 * DMODEL + col) = pack_h2(o[nb][2] * i1, o[nb][3] * i1);
    }
}

// ---------------------------------------------------------------------------
// Residual add + LayerNorm
// ---------------------------------------------------------------------------
__global__ __launch_bounds__(256) void ln_kernel(
    const float* __restrict__ Osrc, const float* __restrict__ X,
    const float* __restrict__ g, const float* __restrict__ beta,
    float* __restrict__ out)
{
    const int row = blockIdx.x;
    const int tid = threadIdx.x;
    const float* o = Osrc + (size_t)row * DMODEL;
    const float* x = X + (size_t)row * DMODEL;

    float v[4];
    float s = 0.f, s2 = 0.f;
#pragma unroll
    for (int i = 0; i < 4; i++) {
        int c = tid + i * 256;
        float t = o[c] + x[c];
        v[i] = t; s += t; s2 += t * t;
    }
#pragma unroll
    for (int off = 16; off; off >>= 1) {
        s  += __shfl_xor_sync(0xffffffffu, s, off);
        s2 += __shfl_xor_sync(0xffffffffu, s2, off);
    }
    __shared__ float red[18];
    int w = tid >> 5;
    if ((tid & 31) == 0) { red[w] = s; red[8 + w] = s2; }
    __syncthreads();
    if (tid == 0) {
        float S = 0.f, S2 = 0.f;
        for (int k = 0; k < 8; k++) { S += red[k]; S2 += red[8 + k]; }
        red[16] = S; red[17] = S2;
    }
    __syncthreads();
    float mu   = red[16] * (1.f / 1024.f);
    float var  = red[17] * (1.f / 1024.f) - mu * mu;
    float rstd = rsqrtf(var + 1e-5f);
#pragma unroll
    for (int i = 0; i < 4; i++) {
        int c = tid + i * 256;
        out[(size_t)row * DMODEL + c] = (v[i] - mu) * rstd * g[c] + beta[c];
    }
}

// ---------------------------------------------------------------------------
extern "C" void kernel_launch(void* const* d_in, const int* in_sizes, int n_in,
                              void* d_out, int out_size)
{
    const float* X  = (const float*)d_in[0];
    const float* Wq = (const float*)d_in[1];
    const float* bq = (const float*)d_in[2];
    const float* Wk = (const float*)d_in[3];
    const float* bk = (const float*)d_in[4];
    const float* Wv = (const float*)d_in[5];
    const float* bv = (const float*)d_in[6];
    const float* Wo = (const float*)d_in[7];
    const float* bo = (const float*)d_in[8];
    const float* lg = (const float*)d_in[9];
    const float* lb = (const float*)d_in[10];
    float* out = (float*)d_out;

    float* Ob = nullptr;
    cudaGetSymbolAddress((void**)&Ob, g_ob);
    __half *xf, *qf, *kf, *vf, *af, *wf;
    cudaGetSymbolAddress((void**)&xf, g_xf);
    cudaGetSymbolAddress((void**)&qf, g_qf);
    cudaGetSymbolAddress((void**)&kf, g_kf);
    cudaGetSymbolAddress((void**)&vf, g_vf);
    cudaGetSymbolAddress((void**)&af, g_af);
    cudaGetSymbolAddress((void**)&wf, g_wf);

    const size_t WS = (size_t)DMODEL * DMODEL;

    conv_all<<<(1 << 21) / 256, 256>>>(X, Wq, Wk, Wv, Wo, xf, wf);

    const int gemm_smem = 3 * 20480;            // 61,440 B
    cudaFuncSetAttribute(gemm_qkv, cudaFuncAttributeMaxDynamicSharedMemorySize, gemm_smem);
    cudaFuncSetAttribute(gemm_out, cudaFuncAttributeMaxDynamicSharedMemorySize, gemm_smem);

    gemm_qkv<<<dim3(24, 32), 256, gemm_smem>>>(xf, wf, bq, bk, bv, qf, kf, vf);

    const int attn_smem = 18432 + 3 * 18432;    // 73,728 B
    cudaFuncSetAttribute(attn_tc, cudaFuncAttributeMaxDynamicSharedMemorySize, attn_smem);
    attn_tc<<<dim3(16, NHEAD, 2), 256, attn_smem>>>(qf, kf, vf, af);

    gemm_out<<<dim3(8, 32), 256, gemm_smem>>>(af, wf + 3 * WS, bo, Ob);

    ln_kernel<<<M_TOK, 256>>>(Ob, X, lg, lb, out);
}